// round 4
// baseline (speedup 1.0000x reference)
#include <cuda_runtime.h>

#define NN 50000
#define EE 800000
#define FOUTC 64
#define CIN 160   // A row: [0:32)=X [32:64)=T1o [64:96)=T1i [96:128)=T2o [128:160)=T2i

// ---- scratch (static device globals; no allocation) ----
__device__ float g_deg_out[NN];
__device__ float g_deg_in[NN];
__device__ int   g_cnt_in[NN];
__device__ int   g_tmp[NN];
__device__ int   g_M;            // #edges with int32 key dst*N+src NOT overflowing
__device__ int   g_csc_ptr[NN + 1];
__device__ int   g_csc_edge[EE];
__device__ int   g_order[EE];   // TRUE (dst,src)-sorted order
__device__ int   g_rs[EE];      // rev_src[p] under the REFERENCE (int32-wrapped) order
__device__ int   g_rd[EE];      // rev_dst[p]
__device__ float g_nin[EE];     // norm_in[p] = 1/deg_in[src[p]]  (positional)
__device__ float g_A[(size_t)NN * CIN];
__device__ float g_Weff[2][CIN * FOUTC];   // [0]=z, [1]=h

// ---------------------------------------------------------------------------
__global__ void k_zero() {
    int i = blockIdx.x * blockDim.x + threadIdx.x;
    if (i < NN) {
        g_deg_out[i] = 0.f; g_deg_in[i] = 0.f;
        g_cnt_in[i] = 0;    g_tmp[i] = 0;
    }
    if (i == 0) g_M = 0;
}

__global__ void k_deg(const int* __restrict__ src, const int* __restrict__ dst,
                      const float* __restrict__ ew) {
    int e = blockIdx.x * blockDim.x + threadIdx.x;
    if (e < EE) {
        float w = ew[e];
        atomicAdd(&g_deg_out[src[e]], w);
        atomicAdd(&g_deg_in[dst[e]], w);
        atomicAdd(&g_cnt_in[dst[e]], 1);
        // jax x64-disabled quirk: argsort key dst*N+src computed in int32 wraps
        // for key >= 2^31; count the non-wrapping edges (they sort AFTER the
        // wrapped ones in the reference order).
        long long key = (long long)dst[e] * NN + (long long)src[e];
        if (key < 2147483648LL) atomicAdd(&g_M, 1);
    }
}

// single-block exclusive scan of cnt_in -> csc_ptr
__global__ void k_scan() {
    __shared__ int sh[1024];
    int tid = threadIdx.x;
    int carry = 0;
    for (int base = 0; base < NN; base += 1024) {
        int idx = base + tid;
        int v = (idx < NN) ? g_cnt_in[idx] : 0;
        sh[tid] = v;
        __syncthreads();
        for (int off = 1; off < 1024; off <<= 1) {
            int t = (tid >= off) ? sh[tid - off] : 0;
            __syncthreads();
            sh[tid] += t;
            __syncthreads();
        }
        if (idx < NN) g_csc_ptr[idx] = carry + sh[tid] - v;
        int tot = sh[1023];
        __syncthreads();
        carry += tot;
    }
    if (tid == 0) g_csc_ptr[NN] = carry;
}

__global__ void k_scatter(const int* __restrict__ dst) {
    int e = blockIdx.x * blockDim.x + threadIdx.x;
    if (e < EE) {
        int d = dst[e];
        int pos = g_csc_ptr[d] + atomicAdd(&g_tmp[d], 1);
        g_csc_edge[pos] = e;
    }
}

// TRUE (dst,src)-sorted order via counting rank per bucket (srcs unique in bucket)
__global__ void k_order(const int* __restrict__ src) {
    int d = blockIdx.x * blockDim.x + threadIdx.x;
    if (d >= NN) return;
    int beg = g_csc_ptr[d], end = g_csc_ptr[d + 1];
    for (int i = beg; i < end; i++) {
        int e = g_csc_edge[i];
        int se = src[e];
        int r = 0;
        for (int j = beg; j < end; j++)
            if (src[g_csc_edge[j]] < se) r++;
        g_order[beg + r] = e;
    }
}

// Reference order = block swap of true order: wrapped-key edges (true positions
// M..E-1) come FIRST. order_ref[p] = order_true[(p + M) mod E].
// norm_in stays positional in the ORIGINAL src array: nin[p] = 1/deg_in[src[p]].
__global__ void k_revlist(const int* __restrict__ src, const int* __restrict__ dst) {
    int p = blockIdx.x * blockDim.x + threadIdx.x;
    if (p < EE) {
        int q = p + g_M;
        if (q >= EE) q -= EE;
        int e = g_order[q];
        g_rs[p] = dst[e];                       // rev_src = dst[order_ref]
        g_rd[p] = src[e];                       // rev_dst = src[order_ref]
        g_nin[p] = 1.0f / g_deg_in[src[p]];     // positional norm_in
    }
}

__global__ void k_copyX(const float* __restrict__ X) {
    int t = blockIdx.x * blockDim.x + threadIdx.x;
    if (t < NN * 32) {
        int n = t >> 5, f = t & 31;
        g_A[(size_t)n * CIN + f] = X[t];
    }
}

// zero T1 accumulators (cols 32..95)
__global__ void k_init1() {
    int t = blockIdx.x * blockDim.x + threadIdx.x;
    if (t < NN * 32) {
        int n = t >> 5, lane = t & 31;
        g_A[(size_t)n * CIN + 32 + lane] = 0.f;
        g_A[(size_t)n * CIN + 64 + lane] = 0.f;
    }
}

// T2 accumulators start at -X (cols 96..159);  T2 = 2*prop(T1) - X
__global__ void k_init2() {
    int t = blockIdx.x * blockDim.x + threadIdx.x;
    if (t < NN * 32) {
        int n = t >> 5, lane = t & 31;
        float mx = -g_A[(size_t)n * CIN + lane];
        g_A[(size_t)n * CIN + 96 + lane] = mx;
        g_A[(size_t)n * CIN + 128 + lane] = mx;
    }
}

// literal scatter prop, forward + reverse in one kernel (2E*32 lanes).
__global__ void k_prop(const int* __restrict__ src, const int* __restrict__ dst,
                       int fi, int fo, int ri, int ro, float coef) {
    long long t = (long long)blockIdx.x * blockDim.x + threadIdx.x;
    int lane = (int)(t & 31);
    long long w = t >> 5;
    if (w < EE) {
        int e = (int)w;
        int s = src[e], d = dst[e];
        float wt = coef / g_deg_out[s];
        atomicAdd(&g_A[(size_t)d * CIN + fo + lane],
                  wt * g_A[(size_t)s * CIN + fi + lane]);
    } else if (w < 2LL * EE) {
        int p = (int)(w - EE);
        int s = g_rs[p], d = g_rd[p];
        float wt = coef * g_nin[p];
        atomicAdd(&g_A[(size_t)d * CIN + ro + lane],
                  wt * g_A[(size_t)s * CIN + ri + lane]);
    }
}

// literal Weff build: W shape (2,3,96,64); only first 32 cin-rows live (H==0)
__global__ void k_weff(const float* __restrict__ Wz, const float* __restrict__ Wh) {
    int t = blockIdx.x * blockDim.x + threadIdx.x;
    if (t >= 32 * 64) return;
    int c = t >> 6, f = t & 63;
#define WI(W, s, k) W[(((s) * 3 + (k)) * 96 + c) * 64 + f]
    g_Weff[0][(0   + c) * 64 + f] = WI(Wz, 0, 0) + WI(Wz, 1, 0);  // X
    g_Weff[0][(32  + c) * 64 + f] = WI(Wz, 0, 1);                 // T1o
    g_Weff[0][(64  + c) * 64 + f] = WI(Wz, 1, 1);                 // T1i
    g_Weff[0][(96  + c) * 64 + f] = WI(Wz, 0, 2);                 // T2o
    g_Weff[0][(128 + c) * 64 + f] = WI(Wz, 1, 2);                 // T2i
    g_Weff[1][(0   + c) * 64 + f] = WI(Wh, 0, 0) + WI(Wh, 1, 0);
    g_Weff[1][(32  + c) * 64 + f] = WI(Wh, 0, 1);
    g_Weff[1][(64  + c) * 64 + f] = WI(Wh, 1, 1);
    g_Weff[1][(96  + c) * 64 + f] = WI(Wh, 0, 2);
    g_Weff[1][(128 + c) * 64 + f] = WI(Wh, 1, 2);
#undef WI
}

// pass 0: out = 1 - sigmoid(A@Wz + bz); pass 1: out *= tanh(A@Wh + bh)
__global__ __launch_bounds__(256) void k_final(const float* __restrict__ bz,
                                               const float* __restrict__ bh,
                                               float* __restrict__ out) {
    __shared__ float ws[CIN * FOUTC];   // 40 KB
    int n = blockIdx.x * blockDim.x + threadIdx.x;

    for (int pass = 0; pass < 2; pass++) {
        const float4* src4 = (const float4*)g_Weff[pass];
        float4* dst4 = (float4*)ws;
        for (int i = threadIdx.x; i < CIN * FOUTC / 4; i += 256) dst4[i] = src4[i];
        __syncthreads();

        if (n < NN) {
            float acc[FOUTC];
            #pragma unroll
            for (int j = 0; j < FOUTC; j++) acc[j] = 0.f;
            const float* a = g_A + (size_t)n * CIN;
            for (int k = 0; k < CIN; k++) {
                float xk = a[k];
                const float4* w4 = (const float4*)(ws + k * FOUTC);
                #pragma unroll
                for (int j = 0; j < FOUTC / 4; j++) {
                    float4 w = w4[j];
                    acc[4 * j + 0] += xk * w.x;
                    acc[4 * j + 1] += xk * w.y;
                    acc[4 * j + 2] += xk * w.z;
                    acc[4 * j + 3] += xk * w.w;
                }
            }
            if (pass == 0) {
                #pragma unroll
                for (int j = 0; j < FOUTC; j++) {
                    float gz = acc[j] + bz[j];
                    out[(size_t)n * FOUTC + j] = 1.0f - 1.0f / (1.0f + expf(-gz));
                }
            } else {
                #pragma unroll
                for (int j = 0; j < FOUTC; j++) {
                    float gh = acc[j] + bh[j];
                    out[(size_t)n * FOUTC + j] *= tanhf(gh);
                }
            }
        }
        __syncthreads();
    }
}

// ---------------------------------------------------------------------------
extern "C" void kernel_launch(void* const* d_in, const int* in_sizes, int n_in,
                              void* d_out, int out_size) {
    const float* X  = (const float*)d_in[0];
    const int*   ei = (const int*)d_in[1];          // [2, E] row-major
    const float* ew = (const float*)d_in[2];
    const float* Wz = (const float*)d_in[3];
    const float* bz = (const float*)d_in[4];
    // d_in[5]=Wr, d_in[6]=br dead: H==0 -> Z*H==0 and H*R==0
    const float* Wh = (const float*)d_in[7];
    const float* bh = (const float*)d_in[8];
    float* out = (float*)d_out;

    const int* src = ei;
    const int* dst = ei + EE;

    k_zero<<<(NN + 255) / 256, 256>>>();
    k_deg<<<(EE + 255) / 256, 256>>>(src, dst, ew);
    k_scan<<<1, 1024>>>();
    k_scatter<<<(EE + 255) / 256, 256>>>(dst);
    k_order<<<(NN + 255) / 256, 256>>>(src);
    k_revlist<<<(EE + 255) / 256, 256>>>(src, dst);
    k_copyX<<<(NN * 32 + 255) / 256, 256>>>(X);
    k_init1<<<(NN * 32 + 255) / 256, 256>>>();
    k_weff<<<(32 * 64 + 255) / 256, 256>>>(Wz, Wh);

    long long lanes = 2LL * EE * 32;
    int pb = (int)((lanes + 255) / 256);
    // T1o (cols 32-63) = fwd(X); T1i (cols 64-95) = rev(X)
    k_prop<<<pb, 256>>>(src, dst, 0, 32, 0, 64, 1.0f);
    k_init2<<<(NN * 32 + 255) / 256, 256>>>();
    // T2o (96-127) = 2*fwd(T1o) - X; T2i (128-159) = 2*rev(T1i) - X
    k_prop<<<pb, 256>>>(src, dst, 32, 96, 64, 128, 2.0f);

    k_final<<<(NN + 255) / 256, 256>>>(bz, bh, out);
}

// round 5
// speedup vs baseline: 1.3124x; 1.3124x over previous
#include <cuda_runtime.h>

#define NN 50000
#define EE 800000
#define FOUTC 64
#define CIN 160   // A row: [0:32)=X [32:64)=T1o [64:96)=T1i [96:128)=T2o [128:160)=T2i

// ---- scratch (static device globals; no allocation) ----
__device__ float g_deg_out[NN];
__device__ float g_deg_in[NN];
__device__ int   g_cnt_in[NN];
__device__ int   g_tmp[NN];
__device__ int   g_M;              // #edges whose int32 key dst*N+src does NOT wrap
__device__ int   g_csc_ptr[NN + 1];
__device__ int   g_csr_ptr[NN + 1];
__device__ int   g_csc_edge[EE];   // bucket-scattered edge ids (arbitrary intra-bucket order)
__device__ float g_wc[EE];         // forward weight at csc slot: 1/deg_out[src]
__device__ int   g_sc[EE];         // src node at csc slot
__device__ float g_w_rev[EE];      // by original edge id: wrap-rotated positional 1/deg_in
__device__ float g_A[(size_t)NN * CIN];
__device__ float g_Weff[2][CIN * FOUTC];   // [0]=z, [1]=h

// ---------------------------------------------------------------------------
__global__ void k_zero() {
    int i = blockIdx.x * blockDim.x + threadIdx.x;
    if (i < NN) {
        g_deg_out[i] = 0.f; g_deg_in[i] = 0.f;
        g_cnt_in[i] = 0;    g_tmp[i] = 0;
    }
    if (i == 0) g_M = 0;
}

__global__ void k_deg(const int* __restrict__ src, const int* __restrict__ dst,
                      const float* __restrict__ ew) {
    int e = blockIdx.x * blockDim.x + threadIdx.x;
    if (e < EE) {
        float w = ew[e];
        atomicAdd(&g_deg_out[src[e]], w);
        atomicAdd(&g_deg_in[dst[e]], w);
        atomicAdd(&g_cnt_in[dst[e]], 1);
        // jax x64-disabled: argsort key dst*N+src wraps in int32 for key >= 2^31;
        // wrapped-key edges sort FIRST. M = count of non-wrapping edges.
        long long key = (long long)dst[e] * NN + (long long)src[e];
        if (key < 2147483648LL) atomicAdd(&g_M, 1);
    }
}

// single-block exclusive scan of cnt_in -> csc_ptr
__global__ void k_scan() {
    __shared__ int sh[1024];
    int tid = threadIdx.x;
    int carry = 0;
    for (int base = 0; base < NN; base += 1024) {
        int idx = base + tid;
        int v = (idx < NN) ? g_cnt_in[idx] : 0;
        sh[tid] = v;
        __syncthreads();
        for (int off = 1; off < 1024; off <<= 1) {
            int t = (tid >= off) ? sh[tid - off] : 0;
            __syncthreads();
            sh[tid] += t;
            __syncthreads();
        }
        if (idx < NN) g_csc_ptr[idx] = carry + sh[tid] - v;
        int tot = sh[1023];
        __syncthreads();
        carry += tot;
    }
    if (tid == 0) g_csc_ptr[NN] = carry;
}

// csr_ptr via binary search (edges sorted by (src,dst) -> src non-decreasing)
__global__ void k_csr(const int* __restrict__ src) {
    int s = blockIdx.x * blockDim.x + threadIdx.x;
    if (s > NN) return;
    if (s == NN) { g_csr_ptr[NN] = EE; return; }
    int lo = 0, hi = EE;
    while (lo < hi) {
        int mid = (lo + hi) >> 1;
        if (src[mid] < s) lo = mid + 1; else hi = mid;
    }
    g_csr_ptr[s] = lo;
}

__global__ void k_scatter(const int* __restrict__ dst) {
    int e = blockIdx.x * blockDim.x + threadIdx.x;
    if (e < EE) {
        int d = dst[e];
        int pos = g_csc_ptr[d] + atomicAdd(&g_tmp[d], 1);
        g_csc_edge[pos] = e;
    }
}

// Per-bucket counting rank gives edge e's TRUE (dst,src)-sorted position
// q = beg + r. Reference order is the wrap rotation: ref position
// p = (q - M) mod E. Positional quirk: w_rev[e] = 1/deg_in[src[p]].
// Also emit forward gather metadata per csc slot.
__global__ void k_order(const int* __restrict__ src) {
    int d = blockIdx.x * blockDim.x + threadIdx.x;
    if (d >= NN) return;
    int beg = g_csc_ptr[d], end = g_csc_ptr[d + 1];
    int M = g_M;
    for (int i = beg; i < end; i++) {
        int e = g_csc_edge[i];
        int se = src[e];
        int r = 0;
        for (int j = beg; j < end; j++)
            if (src[g_csc_edge[j]] < se) r++;
        int p = beg + r - M;
        if (p < 0) p += EE;
        g_w_rev[e] = 1.0f / g_deg_in[src[p]];
        g_wc[i]    = 1.0f / g_deg_out[se];
        g_sc[i]    = se;
    }
}

__global__ void k_copyX(const float* __restrict__ X) {
    int t = blockIdx.x * blockDim.x + threadIdx.x;
    if (t < NN * 32) {
        int n = t >> 5, f = t & 31;
        g_A[(size_t)n * CIN + f] = X[t];
    }
}

// Weff: W shape (2,3,96,64); only first 32 cin-rows live (H==0)
__global__ void k_weff(const float* __restrict__ Wz, const float* __restrict__ Wh) {
    int t = blockIdx.x * blockDim.x + threadIdx.x;
    if (t >= 32 * 64) return;
    int c = t >> 6, f = t & 63;
#define WI(W, s, k) W[(((s) * 3 + (k)) * 96 + c) * 64 + f]
    g_Weff[0][(0   + c) * 64 + f] = WI(Wz, 0, 0) + WI(Wz, 1, 0);  // X
    g_Weff[0][(32  + c) * 64 + f] = WI(Wz, 0, 1);                 // T1o
    g_Weff[0][(64  + c) * 64 + f] = WI(Wz, 1, 1);                 // T1i
    g_Weff[0][(96  + c) * 64 + f] = WI(Wz, 0, 2);                 // T2o
    g_Weff[0][(128 + c) * 64 + f] = WI(Wz, 1, 2);                 // T2i
    g_Weff[1][(0   + c) * 64 + f] = WI(Wh, 0, 0) + WI(Wh, 1, 0);
    g_Weff[1][(32  + c) * 64 + f] = WI(Wh, 0, 1);
    g_Weff[1][(64  + c) * 64 + f] = WI(Wh, 1, 1);
    g_Weff[1][(96  + c) * 64 + f] = WI(Wh, 0, 2);
    g_Weff[1][(128 + c) * 64 + f] = WI(Wh, 1, 2);
#undef WI
}

// Gather prop, one warp per (node, direction). No atomics.
// fwd (w<NN):  out[d][fo+l] = coef * sum_i wc[i]*A[sc[i]][fi+l]   (- X if subx)
// rev (else):  out[s][ro+l] = coef * sum_e w_rev[e]*A[dst[e]][ri+l] (- X if subx)
__global__ __launch_bounds__(256) void k_prop(const int* __restrict__ dst,
                                              int fi, int fo, int ri, int ro,
                                              float coef, int subx) {
    int w = (blockIdx.x * blockDim.x + threadIdx.x) >> 5;
    int lane = threadIdx.x & 31;
    if (w < NN) {
        int d = w;
        int beg = g_csc_ptr[d], end = g_csc_ptr[d + 1];
        float acc = 0.f;
        for (int i = beg; i < end; i++) {
            acc += g_wc[i] * g_A[(size_t)g_sc[i] * CIN + fi + lane];
        }
        float r = coef * acc;
        if (subx) r -= g_A[(size_t)d * CIN + lane];
        g_A[(size_t)d * CIN + fo + lane] = r;
    } else if (w < 2 * NN) {
        int s = w - NN;
        int beg = g_csr_ptr[s], end = g_csr_ptr[s + 1];
        float acc = 0.f;
        for (int e = beg; e < end; e++) {
            acc += g_w_rev[e] * g_A[(size_t)dst[e] * CIN + ri + lane];
        }
        float r = coef * acc;
        if (subx) r -= g_A[(size_t)s * CIN + lane];
        g_A[(size_t)s * CIN + ro + lane] = r;
    }
}

// pass 0: out = 1 - sigmoid(A@Wz + bz); pass 1: out *= tanh(A@Wh + bh)
__global__ __launch_bounds__(256) void k_final(const float* __restrict__ bz,
                                               const float* __restrict__ bh,
                                               float* __restrict__ out) {
    __shared__ float ws[CIN * FOUTC];   // 40 KB
    int n = blockIdx.x * blockDim.x + threadIdx.x;

    for (int pass = 0; pass < 2; pass++) {
        const float4* src4 = (const float4*)g_Weff[pass];
        float4* dst4 = (float4*)ws;
        for (int i = threadIdx.x; i < CIN * FOUTC / 4; i += 256) dst4[i] = src4[i];
        __syncthreads();

        if (n < NN) {
            float acc[FOUTC];
            #pragma unroll
            for (int j = 0; j < FOUTC; j++) acc[j] = 0.f;
            const float* a = g_A + (size_t)n * CIN;
            for (int k = 0; k < CIN; k++) {
                float xk = a[k];
                const float4* w4 = (const float4*)(ws + k * FOUTC);
                #pragma unroll
                for (int j = 0; j < FOUTC / 4; j++) {
                    float4 w = w4[j];
                    acc[4 * j + 0] += xk * w.x;
                    acc[4 * j + 1] += xk * w.y;
                    acc[4 * j + 2] += xk * w.z;
                    acc[4 * j + 3] += xk * w.w;
                }
            }
            if (pass == 0) {
                #pragma unroll
                for (int j = 0; j < FOUTC; j++) {
                    float gz = acc[j] + bz[j];
                    out[(size_t)n * FOUTC + j] = 1.0f - 1.0f / (1.0f + expf(-gz));
                }
            } else {
                #pragma unroll
                for (int j = 0; j < FOUTC; j++) {
                    float gh = acc[j] + bh[j];
                    out[(size_t)n * FOUTC + j] *= tanhf(gh);
                }
            }
        }
        __syncthreads();
    }
}

// ---------------------------------------------------------------------------
extern "C" void kernel_launch(void* const* d_in, const int* in_sizes, int n_in,
                              void* d_out, int out_size) {
    const float* X  = (const float*)d_in[0];
    const int*   ei = (const int*)d_in[1];          // [2, E] row-major
    const float* ew = (const float*)d_in[2];
    const float* Wz = (const float*)d_in[3];
    const float* bz = (const float*)d_in[4];
    // d_in[5]=Wr, d_in[6]=br dead: H==0 -> Z*H==0 and H*R==0
    const float* Wh = (const float*)d_in[7];
    const float* bh = (const float*)d_in[8];
    float* out = (float*)d_out;

    const int* src = ei;
    const int* dst = ei + EE;

    k_zero<<<(NN + 255) / 256, 256>>>();
    k_deg<<<(EE + 255) / 256, 256>>>(src, dst, ew);
    k_scan<<<1, 1024>>>();
    k_csr<<<(NN + 1 + 255) / 256, 256>>>(src);
    k_scatter<<<(EE + 255) / 256, 256>>>(dst);
    k_order<<<(NN + 255) / 256, 256>>>(src);
    k_copyX<<<(NN * 32 + 255) / 256, 256>>>(X);
    k_weff<<<(32 * 64 + 255) / 256, 256>>>(Wz, Wh);

    int prop_blocks = (2 * NN * 32 + 255) / 256;
    // T1o (cols 32-63) = fwd(X); T1i (64-95) = rev(X)
    k_prop<<<prop_blocks, 256>>>(dst, 0, 32, 0, 64, 1.0f, 0);
    // T2o (96-127) = 2*fwd(T1o) - X; T2i (128-159) = 2*rev(T1i) - X
    k_prop<<<prop_blocks, 256>>>(dst, 32, 96, 64, 128, 2.0f, 1);

    k_final<<<(NN + 255) / 256, 256>>>(bz, bh, out);
}

// round 7
// speedup vs baseline: 1.8730x; 1.4271x over previous
#include <cuda_runtime.h>

#define NN 50000
#define EE 800000
#define FOUTC 64
#define CIN 160   // A row: [0:32)=X [32:64)=T1o [64:96)=T1i [96:128)=T2o [128:160)=T2i
#define SCAN_BLOCKS ((NN + 255) / 256)   // 196

// ---- scratch (static device globals; no allocation) ----
__device__ float g_deg_out[NN];
__device__ float g_deg_in[NN];
__device__ int   g_cnt_in[NN];
__device__ int   g_tmp[NN];
__device__ int   g_M;              // #edges whose int32 key dst*N+src does NOT wrap
__device__ int   g_csc_ptr[NN + 1];
__device__ int   g_csr_ptr[NN + 1];
__device__ int   g_blk[SCAN_BLOCKS];
__device__ int   g_blkoff[SCAN_BLOCKS];
__device__ int   g_csc_edge[EE];   // bucket-scattered edge ids (arbitrary intra-bucket order)
__device__ float g_wc[EE];         // forward weight at csc slot: 1/deg_out[src]
__device__ int   g_sc[EE];         // src node at csc slot
__device__ float g_w_rev[EE];      // by original edge id: wrap-rotated positional 1/deg_in
__device__ float g_A[(size_t)NN * CIN];
__device__ float g_Weff[2][CIN * FOUTC];   // [0]=z, [1]=h

// ---------------------------------------------------------------------------
// csr_ptr via binary search (edges sorted by (src,dst) -> src non-decreasing)
__global__ void k_csr(const int* __restrict__ src) {
    int s = blockIdx.x * blockDim.x + threadIdx.x;
    if (s > NN) return;
    if (s == NN) { g_csr_ptr[NN] = EE; return; }
    int lo = 0, hi = EE;
    while (lo < hi) {
        int mid = (lo + hi) >> 1;
        if (src[mid] < s) lo = mid + 1; else hi = mid;
    }
    g_csr_ptr[s] = lo;
}

__global__ void k_zero() {
    int i = blockIdx.x * blockDim.x + threadIdx.x;
    if (i < NN) {
        g_deg_in[i] = 0.f;
        g_cnt_in[i] = 0;
        g_tmp[i] = 0;
    }
    if (i == 0) g_M = 0;
}

// deg_out via CSR gather (no atomics)
__global__ void k_degout(const float* __restrict__ ew) {
    int s = blockIdx.x * blockDim.x + threadIdx.x;
    if (s < NN) {
        int beg = g_csr_ptr[s], end = g_csr_ptr[s + 1];
        float sum = 0.f;
        for (int e = beg; e < end; e++) sum += ew[e];
        g_deg_out[s] = sum;
    }
}

// deg_in / cnt_in scattered atomics; M via ballot + per-block single atomic.
// jax x64-disabled quirk: argsort key dst*N+src wraps in int32 for key >= 2^31;
// wrapped-key edges sort FIRST. M = #non-wrapping edges.
__global__ void k_degin(const int* __restrict__ src, const int* __restrict__ dst,
                        const float* __restrict__ ew) {
    __shared__ int sM;
    if (threadIdx.x == 0) sM = 0;
    __syncthreads();
    int e = blockIdx.x * blockDim.x + threadIdx.x;
    bool nw = false;
    if (e < EE) {
        int d = dst[e];
        atomicAdd(&g_deg_in[d], ew[e]);
        atomicAdd(&g_cnt_in[d], 1);
        long long key = (long long)d * NN + (long long)src[e];
        nw = (key < 2147483648LL);
    }
    unsigned b = __ballot_sync(0xffffffffu, nw);
    if ((threadIdx.x & 31) == 0) atomicAdd(&sM, __popc(b));
    __syncthreads();
    if (threadIdx.x == 0) atomicAdd(&g_M, sM);
}

// ---- multi-block exclusive scan of cnt_in -> csc_ptr ----
__global__ void k_scan1() {
    __shared__ int sh[256];
    int tid = threadIdx.x;
    int gid = blockIdx.x * 256 + tid;
    int v = (gid < NN) ? g_cnt_in[gid] : 0;
    sh[tid] = v;
    __syncthreads();
    for (int off = 1; off < 256; off <<= 1) {
        int t = (tid >= off) ? sh[tid - off] : 0;
        __syncthreads();
        sh[tid] += t;
        __syncthreads();
    }
    if (gid < NN) g_csc_ptr[gid] = sh[tid] - v;   // block-local exclusive
    if (tid == 255) g_blk[blockIdx.x] = sh[255];
}

__global__ void k_scan2() {
    __shared__ int sh[256];
    int tid = threadIdx.x;
    int v = (tid < SCAN_BLOCKS) ? g_blk[tid] : 0;
    sh[tid] = v;
    __syncthreads();
    for (int off = 1; off < 256; off <<= 1) {
        int t = (tid >= off) ? sh[tid - off] : 0;
        __syncthreads();
        sh[tid] += t;
        __syncthreads();
    }
    if (tid < SCAN_BLOCKS) g_blkoff[tid] = sh[tid] - v;
}

__global__ void k_scan3() {
    int gid = blockIdx.x * 256 + threadIdx.x;
    if (gid < NN) g_csc_ptr[gid] += g_blkoff[blockIdx.x];
    if (gid == 0) g_csc_ptr[NN] = EE;
}

__global__ void k_scatter(const int* __restrict__ dst) {
    int e = blockIdx.x * blockDim.x + threadIdx.x;
    if (e < EE) {
        int d = dst[e];
        int pos = g_csc_ptr[d] + atomicAdd(&g_tmp[d], 1);
        g_csc_edge[pos] = e;
    }
}

// Per-bucket counting rank -> TRUE (dst,src)-sorted position q = beg + r.
// Reference order = wrap rotation: ref position p = (q - M) mod E.
// Positional quirk: w_rev[e] = 1/deg_in[src[p]].
__global__ void k_order(const int* __restrict__ src) {
    int d = blockIdx.x * blockDim.x + threadIdx.x;
    if (d >= NN) return;
    int beg = g_csc_ptr[d], end = g_csc_ptr[d + 1];
    int M = g_M;
    for (int i = beg; i < end; i++) {
        int e = g_csc_edge[i];
        int se = src[e];
        int r = 0;
        for (int j = beg; j < end; j++)
            if (src[g_csc_edge[j]] < se) r++;
        int p = beg + r - M;
        if (p < 0) p += EE;
        g_w_rev[e] = 1.0f / g_deg_in[src[p]];
        g_wc[i]    = 1.0f / g_deg_out[se];
        g_sc[i]    = se;
    }
}

__global__ void k_copyX(const float* __restrict__ X) {
    int t = blockIdx.x * blockDim.x + threadIdx.x;
    if (t < NN * 32) {
        int n = t >> 5, f = t & 31;
        g_A[(size_t)n * CIN + f] = X[t];
    }
}

// Weff: W shape (2,3,96,64); only first 32 cin-rows live (H==0)
__global__ void k_weff(const float* __restrict__ Wz, const float* __restrict__ Wh) {
    int t = blockIdx.x * blockDim.x + threadIdx.x;
    if (t >= 32 * 64) return;
    int c = t >> 6, f = t & 63;
#define WI(W, s, k) W[(((s) * 3 + (k)) * 96 + c) * 64 + f]
    g_Weff[0][(0   + c) * 64 + f] = WI(Wz, 0, 0) + WI(Wz, 1, 0);  // X
    g_Weff[0][(32  + c) * 64 + f] = WI(Wz, 0, 1);                 // T1o
    g_Weff[0][(64  + c) * 64 + f] = WI(Wz, 1, 1);                 // T1i
    g_Weff[0][(96  + c) * 64 + f] = WI(Wz, 0, 2);                 // T2o
    g_Weff[0][(128 + c) * 64 + f] = WI(Wz, 1, 2);                 // T2i
    g_Weff[1][(0   + c) * 64 + f] = WI(Wh, 0, 0) + WI(Wh, 1, 0);
    g_Weff[1][(32  + c) * 64 + f] = WI(Wh, 0, 1);
    g_Weff[1][(64  + c) * 64 + f] = WI(Wh, 1, 1);
    g_Weff[1][(96  + c) * 64 + f] = WI(Wh, 0, 2);
    g_Weff[1][(128 + c) * 64 + f] = WI(Wh, 1, 2);
#undef WI
}

// Gather prop, one warp per (node, direction). No atomics.
__global__ __launch_bounds__(256) void k_prop(const int* __restrict__ dst,
                                              int fi, int fo, int ri, int ro,
                                              float coef, int subx) {
    int w = (blockIdx.x * blockDim.x + threadIdx.x) >> 5;
    int lane = threadIdx.x & 31;
    if (w < NN) {
        int d = w;
        int beg = g_csc_ptr[d], end = g_csc_ptr[d + 1];
        float acc = 0.f;
        #pragma unroll 4
        for (int i = beg; i < end; i++) {
            acc += g_wc[i] * g_A[(size_t)g_sc[i] * CIN + fi + lane];
        }
        float r = coef * acc;
        if (subx) r -= g_A[(size_t)d * CIN + lane];
        g_A[(size_t)d * CIN + fo + lane] = r;
    } else if (w < 2 * NN) {
        int s = w - NN;
        int beg = g_csr_ptr[s], end = g_csr_ptr[s + 1];
        float acc = 0.f;
        #pragma unroll 4
        for (int e = beg; e < end; e++) {
            acc += g_w_rev[e] * g_A[(size_t)dst[e] * CIN + ri + lane];
        }
        float r = coef * acc;
        if (subx) r -= g_A[(size_t)s * CIN + lane];
        g_A[(size_t)s * CIN + ro + lane] = r;
    }
}

// 4 tiles of 32 outputs: t=0,1 -> z halves (write out); t=2,3 -> h halves (mul).
__global__ __launch_bounds__(256) void k_final(const float* __restrict__ bz,
                                               const float* __restrict__ bh,
                                               float* __restrict__ out) {
    __shared__ float ws[CIN * 32];   // 20 KB per tile
    int n = blockIdx.x * blockDim.x + threadIdx.x;
    const float* a = g_A + (size_t)n * CIN;

    for (int t = 0; t < 4; t++) {
        int pass = t >> 1;           // 0=z, 1=h
        int half = t & 1;            // column half
        // stage weights: ws[k][c] = Weff[pass][k][half*32 + c]
        const float4* wsrc = (const float4*)g_Weff[pass];
        float4* wdst = (float4*)ws;
        for (int idx = threadIdx.x; idx < CIN * 8; idx += 256) {
            int k = idx >> 3, c4 = idx & 7;
            wdst[idx] = wsrc[k * 16 + half * 8 + c4];
        }
        __syncthreads();

        if (n < NN) {
            float acc[32];
            #pragma unroll
            for (int j = 0; j < 32; j++) acc[j] = 0.f;
            #pragma unroll 4
            for (int k = 0; k < CIN; k += 4) {
                float4 av = *(const float4*)(a + k);
                #pragma unroll
                for (int kk = 0; kk < 4; kk++) {
                    float xk = (&av.x)[kk];
                    const float4* w4 = (const float4*)(ws + (k + kk) * 32);
                    #pragma unroll
                    for (int j = 0; j < 8; j++) {
                        float4 w = w4[j];
                        acc[4 * j + 0] += xk * w.x;
                        acc[4 * j + 1] += xk * w.y;
                        acc[4 * j + 2] += xk * w.z;
                        acc[4 * j + 3] += xk * w.w;
                    }
                }
            }
            float* o = out + (size_t)n * FOUTC + half * 32;
            if (pass == 0) {
                #pragma unroll
                for (int j = 0; j < 32; j++) {
                    float gz = acc[j] + bz[half * 32 + j];
                    o[j] = 1.0f - 1.0f / (1.0f + expf(-gz));
                }
            } else {
                #pragma unroll
                for (int j = 0; j < 32; j++) {
                    float gh = acc[j] + bh[half * 32 + j];
                    o[j] *= tanhf(gh);
                }
            }
        }
        __syncthreads();
    }
}

// ---------------------------------------------------------------------------
extern "C" void kernel_launch(void* const* d_in, const int* in_sizes, int n_in,
                              void* d_out, int out_size) {
    const float* X  = (const float*)d_in[0];
    const int*   ei = (const int*)d_in[1];          // [2, E] row-major
    const float* ew = (const float*)d_in[2];
    const float* Wz = (const float*)d_in[3];
    const float* bz = (const float*)d_in[4];
    // d_in[5]=Wr, d_in[6]=br dead: H==0 -> Z*H==0 and H*R==0
    const float* Wh = (const float*)d_in[7];
    const float* bh = (const float*)d_in[8];
    float* out = (float*)d_out;

    const int* src = ei;
    const int* dst = ei + EE;

    k_csr<<<(NN + 1 + 255) / 256, 256>>>(src);
    k_zero<<<SCAN_BLOCKS, 256>>>();
    k_degout<<<SCAN_BLOCKS, 256>>>(ew);
    k_degin<<<(EE + 255) / 256, 256>>>(src, dst, ew);
    k_scan1<<<SCAN_BLOCKS, 256>>>();
    k_scan2<<<1, 256>>>();
    k_scan3<<<SCAN_BLOCKS, 256>>>();
    k_scatter<<<(EE + 255) / 256, 256>>>(dst);
    k_order<<<SCAN_BLOCKS, 256>>>(src);
    k_copyX<<<(NN * 32 + 255) / 256, 256>>>(X);
    k_weff<<<(32 * 64 + 255) / 256, 256>>>(Wz, Wh);

    int prop_blocks = (2 * NN * 32 + 255) / 256;
    // T1o (cols 32-63) = fwd(X); T1i (64-95) = rev(X)
    k_prop<<<prop_blocks, 256>>>(dst, 0, 32, 0, 64, 1.0f, 0);
    // T2o (96-127) = 2*fwd(T1o) - X; T2i (128-159) = 2*rev(T1i) - X
    k_prop<<<prop_blocks, 256>>>(dst, 32, 96, 64, 128, 2.0f, 1);

    k_final<<<SCAN_BLOCKS, 256>>>(bz, bh, out);
}

// round 8
// speedup vs baseline: 3.2427x; 1.7313x over previous
#include <cuda_runtime.h>

#define NN 50000
#define EE 800000
#define FOUTC 64
#define ASTRIDE 128   // A row: [0:32)=T1o [32:64)=T1i [64:96)=T2o [96:128)=T2i
#define SCAN_BLOCKS ((NN + 255) / 256)   // 196

// ---- scratch (static device globals; no allocation) ----
__device__ float g_deg_out[NN];
__device__ float g_deg_in[NN];
__device__ int   g_cnt_in[NN];
__device__ int   g_tmp[NN];
__device__ int   g_M;              // #edges whose int32 key dst*N+src does NOT wrap
__device__ int   g_csc_ptr[NN + 1];
__device__ int   g_csr_ptr[NN + 1];
__device__ int   g_blk[SCAN_BLOCKS];
__device__ int   g_blkoff[SCAN_BLOCKS];
__device__ int   g_csc_edge[EE];   // bucket-scattered edge ids
__device__ float2 g_fpk[EE];       // per csc slot: {as_float(src), 1/deg_out[src]}
__device__ float2 g_rpk[EE];       // per edge id:  {as_float(dst), wrap-rotated 1/deg_in}
__device__ float g_A[(size_t)NN * ASTRIDE];
__device__ float g_Weff[2][160 * FOUTC];   // [0]=z, [1]=h ; 160 rows = X|T1o|T1i|T2o|T2i

// ---------------------------------------------------------------------------
// csr_ptr via binary search (edges sorted by (src,dst) -> src non-decreasing)
__global__ void k_csr(const int* __restrict__ src) {
    int s = blockIdx.x * blockDim.x + threadIdx.x;
    if (s > NN) return;
    if (s == NN) { g_csr_ptr[NN] = EE; return; }
    int lo = 0, hi = EE;
    while (lo < hi) {
        int mid = (lo + hi) >> 1;
        if (src[mid] < s) lo = mid + 1; else hi = mid;
    }
    g_csr_ptr[s] = lo;
}

__global__ void k_zero() {
    int i = blockIdx.x * blockDim.x + threadIdx.x;
    if (i < NN) {
        g_deg_in[i] = 0.f;
        g_cnt_in[i] = 0;
        g_tmp[i] = 0;
    }
    if (i == 0) g_M = 0;
}

// deg_out via CSR gather (no atomics)
__global__ void k_degout(const float* __restrict__ ew) {
    int s = blockIdx.x * blockDim.x + threadIdx.x;
    if (s < NN) {
        int beg = g_csr_ptr[s], end = g_csr_ptr[s + 1];
        float sum = 0.f;
        for (int e = beg; e < end; e++) sum += ew[e];
        g_deg_out[s] = sum;
    }
}

// deg_in / cnt_in scattered atomics; M via ballot + per-block single atomic.
// jax x64-disabled quirk: argsort key dst*N+src wraps in int32 for key >= 2^31;
// wrapped-key edges sort FIRST. M = #non-wrapping edges.
__global__ void k_degin(const int* __restrict__ src, const int* __restrict__ dst,
                        const float* __restrict__ ew) {
    __shared__ int sM;
    if (threadIdx.x == 0) sM = 0;
    __syncthreads();
    int e = blockIdx.x * blockDim.x + threadIdx.x;
    bool nw = false;
    if (e < EE) {
        int d = dst[e];
        atomicAdd(&g_deg_in[d], ew[e]);
        atomicAdd(&g_cnt_in[d], 1);
        long long key = (long long)d * NN + (long long)src[e];
        nw = (key < 2147483648LL);
    }
    unsigned b = __ballot_sync(0xffffffffu, nw);
    if ((threadIdx.x & 31) == 0) atomicAdd(&sM, __popc(b));
    __syncthreads();
    if (threadIdx.x == 0) atomicAdd(&g_M, sM);
}

// ---- multi-block exclusive scan of cnt_in -> csc_ptr ----
__global__ void k_scan1() {
    __shared__ int sh[256];
    int tid = threadIdx.x;
    int gid = blockIdx.x * 256 + tid;
    int v = (gid < NN) ? g_cnt_in[gid] : 0;
    sh[tid] = v;
    __syncthreads();
    for (int off = 1; off < 256; off <<= 1) {
        int t = (tid >= off) ? sh[tid - off] : 0;
        __syncthreads();
        sh[tid] += t;
        __syncthreads();
    }
    if (gid < NN) g_csc_ptr[gid] = sh[tid] - v;
    if (tid == 255) g_blk[blockIdx.x] = sh[255];
}

__global__ void k_scan2() {
    __shared__ int sh[256];
    int tid = threadIdx.x;
    int v = (tid < SCAN_BLOCKS) ? g_blk[tid] : 0;
    sh[tid] = v;
    __syncthreads();
    for (int off = 1; off < 256; off <<= 1) {
        int t = (tid >= off) ? sh[tid - off] : 0;
        __syncthreads();
        sh[tid] += t;
        __syncthreads();
    }
    if (tid < SCAN_BLOCKS) g_blkoff[tid] = sh[tid] - v;
}

__global__ void k_scan3() {
    int gid = blockIdx.x * 256 + threadIdx.x;
    if (gid < NN) g_csc_ptr[gid] += g_blkoff[blockIdx.x];
    if (gid == 0) g_csc_ptr[NN] = EE;
}

__global__ void k_scatter(const int* __restrict__ dst) {
    int e = blockIdx.x * blockDim.x + threadIdx.x;
    if (e < EE) {
        int d = dst[e];
        int pos = g_csc_ptr[d] + atomicAdd(&g_tmp[d], 1);
        g_csc_edge[pos] = e;
    }
}

// Warp per dst node. Counting rank via shfl all-pairs gives TRUE (dst,src)
// position q = beg + r; reference order = wrap rotation p = (q - M) mod E;
// positional quirk: w_rev[e] = 1/deg_in[src[p]]. Emits packed prop metadata.
__global__ void k_order(const int* __restrict__ src) {
    int w = (blockIdx.x * blockDim.x + threadIdx.x) >> 5;
    int lane = threadIdx.x & 31;
    if (w >= NN) return;
    int d = w;
    int beg = g_csc_ptr[d], end = g_csc_ptr[d + 1];
    int deg = end - beg;
    int M = g_M;
    for (int c0 = 0; c0 < deg; c0 += 32) {
        int i = c0 + lane;
        int e = 0, se = 0x7fffffff;
        if (i < deg) { e = g_csc_edge[beg + i]; se = src[e]; }
        int r = 0;
        for (int c1 = 0; c1 < deg; c1 += 32) {
            int j = c1 + lane;
            int sj = (j < deg) ? src[g_csc_edge[beg + j]] : 0x7fffffff;
            int lim = deg - c1; if (lim > 32) lim = 32;
            for (int l = 0; l < lim; l++) {
                int v = __shfl_sync(0xffffffffu, sj, l);
                if (v < se) r++;
            }
        }
        if (i < deg) {
            int p = beg + r - M;
            if (p < 0) p += EE;
            g_rpk[e] = make_float2(__int_as_float(d), 1.0f / g_deg_in[src[p]]);
            g_fpk[beg + i] = make_float2(__int_as_float(se), 1.0f / g_deg_out[se]);
        }
    }
}

// Gather prop, one warp per (node, direction). No atomics.
// fwd (w<NN): A[d][fo+l] = coef * sum_slot wc*in[sc][fi+l]        (- X[d][l] if subx)
// rev (else): A[s][ro+l] = coef * sum_e  w_rev*in[dst[e]][ri+l]   (- X[s][l] if subx)
__global__ __launch_bounds__(256) void k_prop(const float* __restrict__ in, int istride,
                                              const float* __restrict__ X,
                                              int fi, int fo, int ri, int ro,
                                              float coef, int subx) {
    int w = (blockIdx.x * blockDim.x + threadIdx.x) >> 5;
    int lane = threadIdx.x & 31;
    if (w < NN) {
        int d = w;
        int beg = g_csc_ptr[d], end = g_csc_ptr[d + 1];
        float acc = 0.f;
        #pragma unroll 4
        for (int i = beg; i < end; i++) {
            float2 m = g_fpk[i];
            acc += m.y * in[(size_t)__float_as_int(m.x) * istride + fi + lane];
        }
        float r = coef * acc;
        if (subx) r -= X[(size_t)d * 32 + lane];
        g_A[(size_t)d * ASTRIDE + fo + lane] = r;
    } else if (w < 2 * NN) {
        int s = w - NN;
        int beg = g_csr_ptr[s], end = g_csr_ptr[s + 1];
        float acc = 0.f;
        #pragma unroll 4
        for (int e = beg; e < end; e++) {
            float2 m = g_rpk[e];
            acc += m.y * in[(size_t)__float_as_int(m.x) * istride + ri + lane];
        }
        float r = coef * acc;
        if (subx) r -= X[(size_t)s * 32 + lane];
        g_A[(size_t)s * ASTRIDE + ro + lane] = r;
    }
}

// Weff: W shape (2,3,96,64); only first 32 cin-rows live (H==0)
__global__ void k_weff(const float* __restrict__ Wz, const float* __restrict__ Wh) {
    int t = blockIdx.x * blockDim.x + threadIdx.x;
    if (t >= 32 * 64) return;
    int c = t >> 6, f = t & 63;
#define WI(W, s, k) W[(((s) * 3 + (k)) * 96 + c) * 64 + f]
    g_Weff[0][(0   + c) * 64 + f] = WI(Wz, 0, 0) + WI(Wz, 1, 0);  // X
    g_Weff[0][(32  + c) * 64 + f] = WI(Wz, 0, 1);                 // T1o
    g_Weff[0][(64  + c) * 64 + f] = WI(Wz, 1, 1);                 // T1i
    g_Weff[0][(96  + c) * 64 + f] = WI(Wz, 0, 2);                 // T2o
    g_Weff[0][(128 + c) * 64 + f] = WI(Wz, 1, 2);                 // T2i
    g_Weff[1][(0   + c) * 64 + f] = WI(Wh, 0, 0) + WI(Wh, 1, 0);
    g_Weff[1][(32  + c) * 64 + f] = WI(Wh, 0, 1);
    g_Weff[1][(64  + c) * 64 + f] = WI(Wh, 1, 1);
    g_Weff[1][(96  + c) * 64 + f] = WI(Wh, 0, 2);
    g_Weff[1][(128 + c) * 64 + f] = WI(Wh, 1, 2);
#undef WI
}

// Fused gate GEMM: block = 128 threads (1 node/thread), blockIdx.y = column half.
// Computes z and h together: out = (1 - sigmoid(z)) * tanh(h). Single store.
__global__ __launch_bounds__(128) void k_final(const float* __restrict__ X,
                                               const float* __restrict__ bz,
                                               const float* __restrict__ bh,
                                               float* __restrict__ out) {
    __shared__ float wsz[160 * 32];   // 20 KB
    __shared__ float wsh[160 * 32];   // 20 KB
    int half = blockIdx.y;
    int tid = threadIdx.x;
    // stage both weight tiles: ws[k][c] = Weff[.][k][half*32+c]
    {
        const float4* z4 = (const float4*)g_Weff[0];
        const float4* h4 = (const float4*)g_Weff[1];
        float4* dz = (float4*)wsz;
        float4* dh = (float4*)wsh;
        for (int idx = tid; idx < 160 * 8; idx += 128) {
            int k = idx >> 3, c4 = idx & 7;
            dz[idx] = z4[k * 16 + half * 8 + c4];
            dh[idx] = h4[k * 16 + half * 8 + c4];
        }
    }
    __syncthreads();

    int n = blockIdx.x * 128 + tid;
    if (n >= NN) return;

    const float4* x4 = (const float4*)(X + (size_t)n * 32);
    const float4* a4 = (const float4*)(g_A + (size_t)n * ASTRIDE);

    float accz[32], acch[32];
    #pragma unroll
    for (int j = 0; j < 32; j++) { accz[j] = 0.f; acch[j] = 0.f; }

    #pragma unroll 4
    for (int k = 0; k < 160; k += 4) {
        float4 av = (k < 32) ? x4[k >> 2] : a4[(k - 32) >> 2];
        #pragma unroll
        for (int kk = 0; kk < 4; kk++) {
            float xk = (&av.x)[kk];
            const float4* wz4 = (const float4*)(wsz + (k + kk) * 32);
            const float4* wh4 = (const float4*)(wsh + (k + kk) * 32);
            #pragma unroll
            for (int j = 0; j < 8; j++) {
                float4 wz = wz4[j];
                float4 wh = wh4[j];
                accz[4 * j + 0] += xk * wz.x;  acch[4 * j + 0] += xk * wh.x;
                accz[4 * j + 1] += xk * wz.y;  acch[4 * j + 1] += xk * wh.y;
                accz[4 * j + 2] += xk * wz.z;  acch[4 * j + 2] += xk * wh.z;
                accz[4 * j + 3] += xk * wz.w;  acch[4 * j + 3] += xk * wh.w;
            }
        }
    }

    float* o = out + (size_t)n * FOUTC + half * 32;
    #pragma unroll
    for (int j = 0; j < 32; j++) {
        float gz = accz[j] + bz[half * 32 + j];
        float gh = acch[j] + bh[half * 32 + j];
        float keep = 1.0f - 1.0f / (1.0f + expf(-gz));
        o[j] = keep * tanhf(gh);
    }
}

// ---------------------------------------------------------------------------
extern "C" void kernel_launch(void* const* d_in, const int* in_sizes, int n_in,
                              void* d_out, int out_size) {
    const float* X  = (const float*)d_in[0];
    const int*   ei = (const int*)d_in[1];          // [2, E] row-major
    const float* ew = (const float*)d_in[2];
    const float* Wz = (const float*)d_in[3];
    const float* bz = (const float*)d_in[4];
    // d_in[5]=Wr, d_in[6]=br dead: H==0 -> Z*H==0 and H*R==0
    const float* Wh = (const float*)d_in[7];
    const float* bh = (const float*)d_in[8];
    float* out = (float*)d_out;

    const int* src = ei;
    const int* dst = ei + EE;
    const float* Ag = nullptr;
    cudaGetSymbolAddress((void**)&Ag, g_A);   // host-side, not captured as work

    k_csr<<<(NN + 1 + 255) / 256, 256>>>(src);
    k_zero<<<SCAN_BLOCKS, 256>>>();
    k_degout<<<SCAN_BLOCKS, 256>>>(ew);
    k_degin<<<(EE + 255) / 256, 256>>>(src, dst, ew);
    k_scan1<<<SCAN_BLOCKS, 256>>>();
    k_scan2<<<1, 256>>>();
    k_scan3<<<SCAN_BLOCKS, 256>>>();
    k_scatter<<<(EE + 255) / 256, 256>>>(dst);
    k_order<<<(NN * 32 + 255) / 256, 256>>>(src);
    k_weff<<<(32 * 64 + 255) / 256, 256>>>(Wz, Wh);

    int prop_blocks = (2 * NN * 32 + 255) / 256;
    // T1o (A cols 0-31) = fwd(X); T1i (32-63) = rev(X)
    k_prop<<<prop_blocks, 256>>>(X, 32, X, 0, 0, 0, 32, 1.0f, 0);
    // T2o (64-95) = 2*fwd(T1o) - X; T2i (96-127) = 2*rev(T1i) - X
    k_prop<<<prop_blocks, 256>>>(Ag, ASTRIDE, X, 0, 64, 32, 96, 2.0f, 1);

    dim3 fgrid((NN + 127) / 128, 2);
    k_final<<<fgrid, 128>>>(X, bz, bh, out);
}

// round 10
// speedup vs baseline: 3.6165x; 1.1153x over previous
#include <cuda_runtime.h>

#define NN 50000
#define EE 800000
#define FOUTC 64
#define ASTRIDE 128   // A row: [0:32)=T1o [32:64)=T1i [64:96)=T2o [96:128)=T2i
#define SCAN_BLOCKS ((NN + 255) / 256)   // 196

typedef unsigned long long u64;

// ---- scratch (static device globals; no allocation) ----
__device__ float g_deg_out[NN];
__device__ float g_deg_in[NN];
__device__ int   g_cnt_in[NN];
__device__ int   g_tmp[NN];
__device__ int   g_M;              // #edges whose int32 key dst*N+src does NOT wrap
__device__ int   g_csc_ptr[NN + 1];
__device__ int   g_csr_ptr[NN + 1];
__device__ int   g_blk[SCAN_BLOCKS];
__device__ int   g_blkoff[SCAN_BLOCKS];
__device__ int   g_csc_edge[EE];   // bucket-scattered edge ids
__device__ float2 g_fpk[EE];       // per csc slot: {as_float(src), 1/deg_out[src]}
__device__ float2 g_rpk[EE];       // per edge id:  {as_float(dst), wrap-rotated 1/deg_in}
__device__ float g_A[(size_t)NN * ASTRIDE];
__device__ float g_Weff[2][160 * FOUTC];   // [0]=z, [1]=h ; rows = X|T1o|T1i|T2o|T2i

// ---- f32x2 packed FMA helpers (sm_103a) ----
__device__ __forceinline__ u64 pack2(float x) {
    u64 r;
    asm("mov.b64 %0, {%1, %1};" : "=l"(r) : "f"(x));
    return r;
}
__device__ __forceinline__ void fma2(u64& acc, u64 a, u64 b) {
    asm("fma.rn.f32x2 %0, %1, %2, %0;" : "+l"(acc) : "l"(a), "l"(b));
}
__device__ __forceinline__ void unpack2(float& lo, float& hi, u64 v) {
    asm("mov.b64 {%0, %1}, %2;" : "=f"(lo), "=f"(hi) : "l"(v));
}

// ---------------------------------------------------------------------------
// Merged init: csr_ptr (binary search), deg_out (CSR gather), zeroing, Weff.
__device__ __forceinline__ int lower_bound_src(const int* __restrict__ src, int s) {
    int lo = 0, hi = EE;
    while (lo < hi) {
        int mid = (lo + hi) >> 1;
        if (src[mid] < s) lo = mid + 1; else hi = mid;
    }
    return lo;
}

__global__ void k_init(const int* __restrict__ src, const float* __restrict__ ew,
                       const float* __restrict__ Wz, const float* __restrict__ Wh) {
    int t = blockIdx.x * blockDim.x + threadIdx.x;
    if (t <= NN) {
        int lo = lower_bound_src(src, t);
        g_csr_ptr[t] = lo;
        if (t < NN) {
            int hi = lower_bound_src(src, t + 1);
            float sum = 0.f;
            for (int e = lo; e < hi; e++) sum += ew[e];
            g_deg_out[t] = sum;
            g_deg_in[t] = 0.f;
            g_cnt_in[t] = 0;
            g_tmp[t] = 0;
        }
    }
    if (t == 0) g_M = 0;
    // Weff: W shape (2,3,96,64); only first 32 cin-rows live (H==0)
    if (t < 32 * 64) {
        int c = t >> 6, f = t & 63;
#define WI(W, s, k) W[(((s) * 3 + (k)) * 96 + c) * 64 + f]
        g_Weff[0][(0   + c) * 64 + f] = WI(Wz, 0, 0) + WI(Wz, 1, 0);  // X
        g_Weff[0][(32  + c) * 64 + f] = WI(Wz, 0, 1);                 // T1o
        g_Weff[0][(64  + c) * 64 + f] = WI(Wz, 1, 1);                 // T1i
        g_Weff[0][(96  + c) * 64 + f] = WI(Wz, 0, 2);                 // T2o
        g_Weff[0][(128 + c) * 64 + f] = WI(Wz, 1, 2);                 // T2i
        g_Weff[1][(0   + c) * 64 + f] = WI(Wh, 0, 0) + WI(Wh, 1, 0);
        g_Weff[1][(32  + c) * 64 + f] = WI(Wh, 0, 1);
        g_Weff[1][(64  + c) * 64 + f] = WI(Wh, 1, 1);
        g_Weff[1][(96  + c) * 64 + f] = WI(Wh, 0, 2);
        g_Weff[1][(128 + c) * 64 + f] = WI(Wh, 1, 2);
#undef WI
    }
}

// deg_in / cnt_in scattered atomics; M via ballot + per-block single atomic.
// jax x64-disabled quirk: argsort key dst*N+src wraps in int32 for key >= 2^31;
// wrapped-key edges sort FIRST. M = #non-wrapping edges.
__global__ void k_degin(const int* __restrict__ src, const int* __restrict__ dst,
                        const float* __restrict__ ew) {
    __shared__ int sM;
    if (threadIdx.x == 0) sM = 0;
    __syncthreads();
    int e = blockIdx.x * blockDim.x + threadIdx.x;
    bool nw = false;
    if (e < EE) {
        int d = dst[e];
        atomicAdd(&g_deg_in[d], ew[e]);
        atomicAdd(&g_cnt_in[d], 1);
        long long key = (long long)d * NN + (long long)src[e];
        nw = (key < 2147483648LL);
    }
    unsigned b = __ballot_sync(0xffffffffu, nw);
    if ((threadIdx.x & 31) == 0) atomicAdd(&sM, __popc(b));
    __syncthreads();
    if (threadIdx.x == 0) atomicAdd(&g_M, sM);
}

// ---- multi-block exclusive scan of cnt_in -> csc_ptr ----
__global__ void k_scan1() {
    __shared__ int sh[256];
    int tid = threadIdx.x;
    int gid = blockIdx.x * 256 + tid;
    int v = (gid < NN) ? g_cnt_in[gid] : 0;
    sh[tid] = v;
    __syncthreads();
    for (int off = 1; off < 256; off <<= 1) {
        int t = (tid >= off) ? sh[tid - off] : 0;
        __syncthreads();
        sh[tid] += t;
        __syncthreads();
    }
    if (gid < NN) g_csc_ptr[gid] = sh[tid] - v;
    if (tid == 255) g_blk[blockIdx.x] = sh[255];
}

__global__ void k_scan2() {
    __shared__ int sh[256];
    int tid = threadIdx.x;
    int v = (tid < SCAN_BLOCKS) ? g_blk[tid] : 0;
    sh[tid] = v;
    __syncthreads();
    for (int off = 1; off < 256; off <<= 1) {
        int t = (tid >= off) ? sh[tid - off] : 0;
        __syncthreads();
        sh[tid] += t;
        __syncthreads();
    }
    if (tid < SCAN_BLOCKS) g_blkoff[tid] = sh[tid] - v;
}

__global__ void k_scan3() {
    int gid = blockIdx.x * 256 + threadIdx.x;
    if (gid < NN) g_csc_ptr[gid] += g_blkoff[blockIdx.x];
    if (gid == 0) g_csc_ptr[NN] = EE;
}

__global__ void k_scatter(const int* __restrict__ dst) {
    int e = blockIdx.x * blockDim.x + threadIdx.x;
    if (e < EE) {
        int d = dst[e];
        int pos = g_csc_ptr[d] + atomicAdd(&g_tmp[d], 1);
        g_csc_edge[pos] = e;
    }
}

// Warp per dst node. Counting rank via shfl all-pairs gives TRUE (dst,src)
// position q = beg + r; reference order = wrap rotation p = (q - M) mod E;
// positional quirk: w_rev[e] = 1/deg_in[src[p]]. Emits packed prop metadata.
__global__ void k_order(const int* __restrict__ src) {
    int w = (blockIdx.x * blockDim.x + threadIdx.x) >> 5;
    int lane = threadIdx.x & 31;
    if (w >= NN) return;
    int d = w;
    int beg = g_csc_ptr[d], end = g_csc_ptr[d + 1];
    int deg = end - beg;
    int M = g_M;
    for (int c0 = 0; c0 < deg; c0 += 32) {
        int i = c0 + lane;
        int e = 0, se = 0x7fffffff;
        if (i < deg) { e = g_csc_edge[beg + i]; se = src[e]; }
        int r = 0;
        for (int c1 = 0; c1 < deg; c1 += 32) {
            int j = c1 + lane;
            int sj = (j < deg) ? src[g_csc_edge[beg + j]] : 0x7fffffff;
            int lim = deg - c1; if (lim > 32) lim = 32;
            for (int l = 0; l < lim; l++) {
                int v = __shfl_sync(0xffffffffu, sj, l);
                if (v < se) r++;
            }
        }
        if (i < deg) {
            int p = beg + r - M;
            if (p < 0) p += EE;
            g_rpk[e] = make_float2(__int_as_float(d), 1.0f / g_deg_in[src[p]]);
            g_fpk[beg + i] = make_float2(__int_as_float(se), 1.0f / g_deg_out[se]);
        }
    }
}

// Gather prop, one warp per (node, direction). No atomics.
__global__ __launch_bounds__(256) void k_prop(const float* __restrict__ in, int istride,
                                              const float* __restrict__ X,
                                              int fi, int fo, int ri, int ro,
                                              float coef, int subx) {
    int w = (blockIdx.x * blockDim.x + threadIdx.x) >> 5;
    int lane = threadIdx.x & 31;
    if (w < NN) {
        int d = w;
        int beg = g_csc_ptr[d], end = g_csc_ptr[d + 1];
        float acc = 0.f;
        #pragma unroll 4
        for (int i = beg; i < end; i++) {
            float2 m = g_fpk[i];
            acc += m.y * in[(size_t)__float_as_int(m.x) * istride + fi + lane];
        }
        float r = coef * acc;
        if (subx) r -= X[(size_t)d * 32 + lane];
        g_A[(size_t)d * ASTRIDE + fo + lane] = r;
    } else if (w < 2 * NN) {
        int s = w - NN;
        int beg = g_csr_ptr[s], end = g_csr_ptr[s + 1];
        float acc = 0.f;
        #pragma unroll 4
        for (int e = beg; e < end; e++) {
            float2 m = g_rpk[e];
            acc += m.y * in[(size_t)__float_as_int(m.x) * istride + ri + lane];
        }
        float r = coef * acc;
        if (subx) r -= X[(size_t)s * 32 + lane];
        g_A[(size_t)s * ASTRIDE + ro + lane] = r;
    }
}

// Fused gate GEMM on packed f32x2: 128 threads, 2 nodes/thread,
// blockIdx.y = column half. out = (1 - sigmoid(z)) * tanh(h).
__global__ __launch_bounds__(128) void k_final(const float* __restrict__ X,
                                               const float* __restrict__ bz,
                                               const float* __restrict__ bh,
                                               float* __restrict__ out) {
    __shared__ float wsz[160 * 32];   // 20 KB
    __shared__ float wsh[160 * 32];   // 20 KB
    int half = blockIdx.y;
    int tid = threadIdx.x;
    {
        const float4* z4 = (const float4*)g_Weff[0];
        const float4* h4 = (const float4*)g_Weff[1];
        float4* dz = (float4*)wsz;
        float4* dh = (float4*)wsh;
        for (int idx = tid; idx < 160 * 8; idx += 128) {
            int k = idx >> 3, c4 = idx & 7;
            dz[idx] = z4[k * 16 + half * 8 + c4];
            dh[idx] = h4[k * 16 + half * 8 + c4];
        }
    }
    __syncthreads();

    int n0 = blockIdx.x * 256 + tid;
    int n1 = n0 + 128;
    bool v0 = n0 < NN, v1 = n1 < NN;
    const float4* x0 = (const float4*)(X + (size_t)n0 * 32);
    const float4* a0 = (const float4*)(g_A + (size_t)n0 * ASTRIDE);
    const float4* x1 = (const float4*)(X + (size_t)n1 * 32);
    const float4* a1 = (const float4*)(g_A + (size_t)n1 * ASTRIDE);

    u64 az0[16], ah0[16], az1[16], ah1[16];
    #pragma unroll
    for (int j = 0; j < 16; j++) { az0[j] = 0ULL; ah0[j] = 0ULL; az1[j] = 0ULL; ah1[j] = 0ULL; }

    const float4 zero4 = make_float4(0.f, 0.f, 0.f, 0.f);
    for (int k4 = 0; k4 < 40; k4++) {
        float4 av0 = v0 ? (k4 < 8 ? x0[k4] : a0[k4 - 8]) : zero4;
        float4 av1 = v1 ? (k4 < 8 ? x1[k4] : a1[k4 - 8]) : zero4;
        #pragma unroll
        for (int kk = 0; kk < 4; kk++) {
            u64 xx0 = pack2((&av0.x)[kk]);
            u64 xx1 = pack2((&av1.x)[kk]);
            const u64* wz2 = (const u64*)(wsz + (k4 * 4 + kk) * 32);
            const u64* wh2 = (const u64*)(wsh + (k4 * 4 + kk) * 32);
            #pragma unroll
            for (int j = 0; j < 16; j++) {
                u64 w = wz2[j];
                fma2(az0[j], w, xx0);
                fma2(az1[j], w, xx1);
                u64 v = wh2[j];
                fma2(ah0[j], v, xx0);
                fma2(ah1[j], v, xx1);
            }
        }
    }

    if (v0) {
        float* o = out + (size_t)n0 * FOUTC + half * 32;
        #pragma unroll
        for (int j = 0; j < 16; j++) {
            float zl, zh, hl, hh;
            unpack2(zl, zh, az0[j]);
            unpack2(hl, hh, ah0[j]);
            float gz0 = zl + bz[half * 32 + 2 * j];
            float gz1 = zh + bz[half * 32 + 2 * j + 1];
            float gh0 = hl + bh[half * 32 + 2 * j];
            float gh1 = hh + bh[half * 32 + 2 * j + 1];
            o[2 * j]     = (1.0f - 1.0f / (1.0f + expf(-gz0))) * tanhf(gh0);
            o[2 * j + 1] = (1.0f - 1.0f / (1.0f + expf(-gz1))) * tanhf(gh1);
        }
    }
    if (v1) {
        float* o = out + (size_t)n1 * FOUTC + half * 32;
        #pragma unroll
        for (int j = 0; j < 16; j++) {
            float zl, zh, hl, hh;
            unpack2(zl, zh, az1[j]);
            unpack2(hl, hh, ah1[j]);
            float gz0 = zl + bz[half * 32 + 2 * j];
            float gz1 = zh + bz[half * 32 + 2 * j + 1];
            float gh0 = hl + bh[half * 32 + 2 * j];
            float gh1 = hh + bh[half * 32 + 2 * j + 1];
            o[2 * j]     = (1.0f - 1.0f / (1.0f + expf(-gz0))) * tanhf(gh0);
            o[2 * j + 1] = (1.0f - 1.0f / (1.0f + expf(-gz1))) * tanhf(gh1);
        }
    }
}

// ---------------------------------------------------------------------------
extern "C" void kernel_launch(void* const* d_in, const int* in_sizes, int n_in,
                              void* d_out, int out_size) {
    const float* X  = (const float*)d_in[0];
    const int*   ei = (const int*)d_in[1];          // [2, E] row-major
    const float* ew = (const float*)d_in[2];
    const float* Wz = (const float*)d_in[3];
    const float* bz = (const float*)d_in[4];
    // d_in[5]=Wr, d_in[6]=br dead: H==0 -> Z*H==0 and H*R==0
    const float* Wh = (const float*)d_in[7];
    const float* bh = (const float*)d_in[8];
    float* out = (float*)d_out;

    const int* src = ei;
    const int* dst = ei + EE;
    const float* Ag = nullptr;
    cudaGetSymbolAddress((void**)&Ag, g_A);   // host-side query, no device work

    k_init<<<(NN + 1 + 255) / 256, 256>>>(src, ew, Wz, Wh);
    k_degin<<<(EE + 255) / 256, 256>>>(src, dst, ew);
    k_scan1<<<SCAN_BLOCKS, 256>>>();
    k_scan2<<<1, 256>>>();
    k_scan3<<<SCAN_BLOCKS, 256>>>();
    k_scatter<<<(EE + 255) / 256, 256>>>(dst);
    k_order<<<(NN * 32 + 255) / 256, 256>>>(src);

    int prop_blocks = (2 * NN * 32 + 255) / 256;
    // T1o (A cols 0-31) = fwd(X); T1i (32-63) = rev(X)
    k_prop<<<prop_blocks, 256>>>(X, 32, X, 0, 0, 0, 32, 1.0f, 0);
    // T2o (64-95) = 2*fwd(T1o) - X; T2i (96-127) = 2*rev(T1i) - X
    k_prop<<<prop_blocks, 256>>>(Ag, ASTRIDE, X, 0, 64, 32, 96, 2.0f, 1);

    dim3 fgrid((NN + 255) / 256, 2);
    k_final<<<fgrid, 128>>>(X, bz, bh, out);
}

// round 11
// speedup vs baseline: 3.6859x; 1.0192x over previous
#include <cuda_runtime.h>

#define NN 50000
#define EE 800000
#define FOUTC 64
#define ASTRIDE 128   // A row: [0:32)=T1o [32:64)=T1i [64:96)=T2o [96:128)=T2i
#define SCAN_BLOCKS ((NN + 255) / 256)   // 196

typedef unsigned long long u64;

// ---- scratch (static device globals; no allocation) ----
__device__ float g_deg_out[NN];
__device__ float g_deg_in[NN];
__device__ int   g_cnt_in[NN];
__device__ int   g_tmp[NN];
__device__ int   g_M;              // #edges whose int32 key dst*N+src does NOT wrap
__device__ int   g_csc_ptr[NN + 1];
__device__ int   g_csr_ptr[NN + 1];
__device__ int   g_blk[SCAN_BLOCKS];
__device__ int   g_blkoff[SCAN_BLOCKS];
__device__ int   g_csc_edge[EE];   // bucket-scattered edge ids
__device__ float2 g_fpk[EE];       // per csc slot: {as_float(src), 1/deg_out[src]}
__device__ float2 g_rpk[EE];       // per edge id:  {as_float(dst), wrap-rotated 1/deg_in}
__device__ float g_A[(size_t)NN * ASTRIDE];
__device__ float g_Weff[2][160 * FOUTC];   // [0]=z, [1]=h ; rows = X|T1o|T1i|T2o|T2i

// ---- f32x2 packed FMA helpers (sm_103a) ----
__device__ __forceinline__ u64 pack2(float x) {
    u64 r;
    asm("mov.b64 %0, {%1, %1};" : "=l"(r) : "f"(x));
    return r;
}
__device__ __forceinline__ void fma2(u64& acc, u64 a, u64 b) {
    asm("fma.rn.f32x2 %0, %1, %2, %0;" : "+l"(acc) : "l"(a), "l"(b));
}
__device__ __forceinline__ void unpack2(float& lo, float& hi, u64 v) {
    asm("mov.b64 {%0, %1}, %2;" : "=f"(lo), "=f"(hi) : "l"(v));
}

// ---------------------------------------------------------------------------
__device__ __forceinline__ int lower_bound_src(const int* __restrict__ src, int s) {
    int lo = 0, hi = EE;
    while (lo < hi) {
        int mid = (lo + hi) >> 1;
        if (src[mid] < s) lo = mid + 1; else hi = mid;
    }
    return lo;
}

// Merged init: csr_ptr (binary search), deg_out (CSR gather), zeroing, Weff.
__global__ void k_init(const int* __restrict__ src, const float* __restrict__ ew,
                       const float* __restrict__ Wz, const float* __restrict__ Wh) {
    int t = blockIdx.x * blockDim.x + threadIdx.x;
    if (t <= NN) {
        int lo = lower_bound_src(src, t);
        g_csr_ptr[t] = lo;
        if (t < NN) {
            int hi = lower_bound_src(src, t + 1);
            float sum = 0.f;
            for (int e = lo; e < hi; e++) sum += ew[e];
            g_deg_out[t] = sum;
            g_deg_in[t] = 0.f;
            g_cnt_in[t] = 0;
            g_tmp[t] = 0;
        }
    }
    if (t == 0) g_M = 0;
    // Weff: W shape (2,3,96,64); only first 32 cin-rows live (H==0)
    if (t < 32 * 64) {
        int c = t >> 6, f = t & 63;
#define WI(W, s, k) W[(((s) * 3 + (k)) * 96 + c) * 64 + f]
        g_Weff[0][(0   + c) * 64 + f] = WI(Wz, 0, 0) + WI(Wz, 1, 0);  // X
        g_Weff[0][(32  + c) * 64 + f] = WI(Wz, 0, 1);                 // T1o
        g_Weff[0][(64  + c) * 64 + f] = WI(Wz, 1, 1);                 // T1i
        g_Weff[0][(96  + c) * 64 + f] = WI(Wz, 0, 2);                 // T2o
        g_Weff[0][(128 + c) * 64 + f] = WI(Wz, 1, 2);                 // T2i
        g_Weff[1][(0   + c) * 64 + f] = WI(Wh, 0, 0) + WI(Wh, 1, 0);
        g_Weff[1][(32  + c) * 64 + f] = WI(Wh, 0, 1);
        g_Weff[1][(64  + c) * 64 + f] = WI(Wh, 1, 1);
        g_Weff[1][(96  + c) * 64 + f] = WI(Wh, 0, 2);
        g_Weff[1][(128 + c) * 64 + f] = WI(Wh, 1, 2);
#undef WI
    }
}

// deg_in / cnt_in scattered atomics.
__global__ void k_degin(const int* __restrict__ dst, const float* __restrict__ ew) {
    int e = blockIdx.x * blockDim.x + threadIdx.x;
    if (e < EE) {
        int d = dst[e];
        atomicAdd(&g_deg_in[d], ew[e]);
        atomicAdd(&g_cnt_in[d], 1);
    }
}

// ---- multi-block exclusive scan of cnt_in -> csc_ptr ----
__global__ void k_scan1() {
    __shared__ int sh[256];
    int tid = threadIdx.x;
    int gid = blockIdx.x * 256 + tid;
    int v = (gid < NN) ? g_cnt_in[gid] : 0;
    sh[tid] = v;
    __syncthreads();
    for (int off = 1; off < 256; off <<= 1) {
        int t = (tid >= off) ? sh[tid - off] : 0;
        __syncthreads();
        sh[tid] += t;
        __syncthreads();
    }
    if (gid < NN) g_csc_ptr[gid] = sh[tid] - v;
    if (tid == 255) g_blk[blockIdx.x] = sh[255];
}

__global__ void k_scan2() {
    __shared__ int sh[256];
    int tid = threadIdx.x;
    int v = (tid < SCAN_BLOCKS) ? g_blk[tid] : 0;
    sh[tid] = v;
    __syncthreads();
    for (int off = 1; off < 256; off <<= 1) {
        int t = (tid >= off) ? sh[tid - off] : 0;
        __syncthreads();
        sh[tid] += t;
        __syncthreads();
    }
    if (tid < SCAN_BLOCKS) g_blkoff[tid] = sh[tid] - v;
}

__global__ void k_scan3() {
    int gid = blockIdx.x * 256 + threadIdx.x;
    if (gid < NN) g_csc_ptr[gid] += g_blkoff[blockIdx.x];
    if (gid == 0) g_csc_ptr[NN] = EE;
}

// Scatter + M-count (ballot). jax x64-disabled quirk: argsort key dst*N+src
// wraps in int32 for key >= 2^31; wrapped-key edges sort FIRST.
__global__ void k_scatter(const int* __restrict__ src, const int* __restrict__ dst) {
    __shared__ int sM;
    if (threadIdx.x == 0) sM = 0;
    __syncthreads();
    int e = blockIdx.x * blockDim.x + threadIdx.x;
    bool nw = false;
    if (e < EE) {
        int d = dst[e];
        int pos = g_csc_ptr[d] + atomicAdd(&g_tmp[d], 1);
        g_csc_edge[pos] = e;
        long long key = (long long)d * NN + (long long)src[e];
        nw = (key < 2147483648LL);
    }
    unsigned b = __ballot_sync(0xffffffffu, nw);
    if ((threadIdx.x & 31) == 0) atomicAdd(&sM, __popc(b));
    __syncthreads();
    if (threadIdx.x == 0) atomicAdd(&g_M, sM);
}

// Warp per dst node. Counting rank via shfl all-pairs gives TRUE (dst,src)
// position q = beg + r; reference order = wrap rotation p = (q - M) mod E;
// positional quirk: w_rev[e] = 1/deg_in[src[p]]. Emits packed prop metadata.
__global__ void k_order(const int* __restrict__ src) {
    int w = (blockIdx.x * blockDim.x + threadIdx.x) >> 5;
    int lane = threadIdx.x & 31;
    if (w >= NN) return;
    int d = w;
    int beg = g_csc_ptr[d], end = g_csc_ptr[d + 1];
    int deg = end - beg;
    int M = g_M;
    for (int c0 = 0; c0 < deg; c0 += 32) {
        int i = c0 + lane;
        int e = 0, se = 0x7fffffff;
        if (i < deg) { e = g_csc_edge[beg + i]; se = src[e]; }
        int r = 0;
        for (int c1 = 0; c1 < deg; c1 += 32) {
            int j = c1 + lane;
            int sj = (j < deg) ? src[g_csc_edge[beg + j]] : 0x7fffffff;
            int lim = deg - c1; if (lim > 32) lim = 32;
            for (int l = 0; l < lim; l++) {
                int v = __shfl_sync(0xffffffffu, sj, l);
                if (v < se) r++;
            }
        }
        if (i < deg) {
            int p = beg + r - M;
            if (p < 0) p += EE;
            g_rpk[e] = make_float2(__int_as_float(d), 1.0f / g_deg_in[src[p]]);
            g_fpk[beg + i] = make_float2(__int_as_float(se), 1.0f / g_deg_out[se]);
        }
    }
}

// Gather prop, one warp per (node, direction). No atomics.
__global__ __launch_bounds__(256) void k_prop(const float* __restrict__ in, int istride,
                                              const float* __restrict__ X,
                                              int fi, int fo, int ri, int ro,
                                              float coef, int subx) {
    int w = (blockIdx.x * blockDim.x + threadIdx.x) >> 5;
    int lane = threadIdx.x & 31;
    if (w < NN) {
        int d = w;
        int beg = g_csc_ptr[d], end = g_csc_ptr[d + 1];
        float acc = 0.f;
        #pragma unroll 4
        for (int i = beg; i < end; i++) {
            float2 m = g_fpk[i];
            acc += m.y * in[(size_t)__float_as_int(m.x) * istride + fi + lane];
        }
        float r = coef * acc;
        if (subx) r -= X[(size_t)d * 32 + lane];
        g_A[(size_t)d * ASTRIDE + fo + lane] = r;
    } else if (w < 2 * NN) {
        int s = w - NN;
        int beg = g_csr_ptr[s], end = g_csr_ptr[s + 1];
        float acc = 0.f;
        #pragma unroll 4
        for (int e = beg; e < end; e++) {
            float2 m = g_rpk[e];
            acc += m.y * in[(size_t)__float_as_int(m.x) * istride + ri + lane];
        }
        float r = coef * acc;
        if (subx) r -= X[(size_t)s * 32 + lane];
        g_A[(size_t)s * ASTRIDE + ro + lane] = r;
    }
}

// Fused gate GEMM on packed f32x2: 128 threads, 2 nodes/thread,
// blockIdx.y = column half. Weight tile interleaved [k][g][z0 z1 h0 h1]
// so one LDS.128 feeds 4 FFMA2. out = (1 - sigmoid(z)) * tanh(h).
__global__ __launch_bounds__(128) void k_final(const float* __restrict__ X,
                                               const float* __restrict__ bz,
                                               const float* __restrict__ bh,
                                               float* __restrict__ out) {
    __shared__ float4 wzh[160 * 16];   // 40 KB: [k][g] -> {z(2g), z(2g+1), h(2g), h(2g+1)}
    int half = blockIdx.y;
    int tid = threadIdx.x;
    {
        const float2* z2 = (const float2*)g_Weff[0];
        const float2* h2 = (const float2*)g_Weff[1];
        for (int idx = tid; idx < 160 * 16; idx += 128) {
            int k = idx >> 4, g = idx & 15;
            float2 z = z2[k * 32 + half * 16 + g];
            float2 h = h2[k * 32 + half * 16 + g];
            wzh[idx] = make_float4(z.x, z.y, h.x, h.y);
        }
    }
    __syncthreads();

    int n0 = blockIdx.x * 256 + tid;
    int n1 = n0 + 128;
    bool v0 = n0 < NN, v1 = n1 < NN;
    const float4* x0 = (const float4*)(X + (size_t)n0 * 32);
    const float4* a0 = (const float4*)(g_A + (size_t)n0 * ASTRIDE);
    const float4* x1 = (const float4*)(X + (size_t)n1 * 32);
    const float4* a1 = (const float4*)(g_A + (size_t)n1 * ASTRIDE);

    u64 az0[16], ah0[16], az1[16], ah1[16];
    #pragma unroll
    for (int g = 0; g < 16; g++) { az0[g] = 0ULL; ah0[g] = 0ULL; az1[g] = 0ULL; ah1[g] = 0ULL; }

    const float4 zero4 = make_float4(0.f, 0.f, 0.f, 0.f);
    for (int k4 = 0; k4 < 40; k4++) {
        float4 av0 = v0 ? (k4 < 8 ? x0[k4] : a0[k4 - 8]) : zero4;
        float4 av1 = v1 ? (k4 < 8 ? x1[k4] : a1[k4 - 8]) : zero4;
        #pragma unroll
        for (int kk = 0; kk < 4; kk++) {
            u64 xx0 = pack2((&av0.x)[kk]);
            u64 xx1 = pack2((&av1.x)[kk]);
            const u64* wp = (const u64*)(wzh + (k4 * 4 + kk) * 16);
            #pragma unroll
            for (int g = 0; g < 16; g++) {
                u64 wz = wp[2 * g];
                u64 wh = wp[2 * g + 1];
                fma2(az0[g], wz, xx0);
                fma2(az1[g], wz, xx1);
                fma2(ah0[g], wh, xx0);
                fma2(ah1[g], wh, xx1);
            }
        }
    }

    #pragma unroll
    for (int which = 0; which < 2; which++) {
        bool v = which ? v1 : v0;
        if (!v) continue;
        int n = which ? n1 : n0;
        const u64* az = which ? az1 : az0;
        const u64* ah = which ? ah1 : ah0;
        float* o = out + (size_t)n * FOUTC + half * 32;
        #pragma unroll
        for (int g = 0; g < 16; g++) {
            float zl, zh, hl, hh;
            unpack2(zl, zh, az[g]);
            unpack2(hl, hh, ah[g]);
            float gz0 = zl + bz[half * 32 + 2 * g];
            float gz1 = zh + bz[half * 32 + 2 * g + 1];
            float gh0 = hl + bh[half * 32 + 2 * g];
            float gh1 = hh + bh[half * 32 + 2 * g + 1];
            // keep = 1 - sigmoid(gz); tanh via exp: 2/(1+e^-2x) - 1
            float k0 = 1.0f - 1.0f / (1.0f + __expf(-gz0));
            float k1 = 1.0f - 1.0f / (1.0f + __expf(-gz1));
            float t0 = 2.0f / (1.0f + __expf(-2.0f * gh0)) - 1.0f;
            float t1 = 2.0f / (1.0f + __expf(-2.0f * gh1)) - 1.0f;
            o[2 * g]     = k0 * t0;
            o[2 * g + 1] = k1 * t1;
        }
    }
}

// ---------------------------------------------------------------------------
extern "C" void kernel_launch(void* const* d_in, const int* in_sizes, int n_in,
                              void* d_out, int out_size) {
    const float* X  = (const float*)d_in[0];
    const int*   ei = (const int*)d_in[1];          // [2, E] row-major
    const float* ew = (const float*)d_in[2];
    const float* Wz = (const float*)d_in[3];
    const float* bz = (const float*)d_in[4];
    // d_in[5]=Wr, d_in[6]=br dead: H==0 -> Z*H==0 and H*R==0
    const float* Wh = (const float*)d_in[7];
    const float* bh = (const float*)d_in[8];
    float* out = (float*)d_out;

    const int* src = ei;
    const int* dst = ei + EE;
    const float* Ag = nullptr;
    cudaGetSymbolAddress((void**)&Ag, g_A);   // host-side query, no device work

    k_init<<<(NN + 1 + 255) / 256, 256>>>(src, ew, Wz, Wh);
    k_degin<<<(EE + 255) / 256, 256>>>(dst, ew);
    k_scan1<<<SCAN_BLOCKS, 256>>>();
    k_scan2<<<1, 256>>>();
    k_scan3<<<SCAN_BLOCKS, 256>>>();
    k_scatter<<<(EE + 255) / 256, 256>>>(src, dst);
    k_order<<<(NN * 32 + 255) / 256, 256>>>(src);

    int prop_blocks = (2 * NN * 32 + 255) / 256;
    // T1o (A cols 0-31) = fwd(X); T1i (32-63) = rev(X)
    k_prop<<<prop_blocks, 256>>>(X, 32, X, 0, 0, 0, 32, 1.0f, 0);
    // T2o (64-95) = 2*fwd(T1o) - X; T2i (96-127) = 2*rev(T1i) - X
    k_prop<<<prop_blocks, 256>>>(Ag, ASTRIDE, X, 0, 64, 32, 96, 2.0f, 1);

    dim3 fgrid((NN + 255) / 256, 2);
    k_final<<<fgrid, 128>>>(X, bz, bh, out);
}

// round 12
// speedup vs baseline: 3.7564x; 1.0191x over previous
#include <cuda_runtime.h>

#define NN 50000
#define EE 800000
#define FOUTC 64
#define ASTRIDE 128   // A row: [0:32)=T1o [32:64)=T1i [64:96)=T2o [96:128)=T2i
#define SCAN_BLOCKS ((NN + 255) / 256)   // 196

typedef unsigned long long u64;

// ---- scratch (static device globals; no allocation) ----
__device__ float g_deg_out[NN];
__device__ float g_deg_in[NN];
__device__ int   g_cnt_in[NN];
__device__ int   g_tmp[NN];
__device__ int   g_M;              // #edges whose int32 key dst*N+src does NOT wrap
__device__ int   g_csc_ptr[NN + 1];
__device__ int   g_csr_ptr[NN + 1];
__device__ int   g_blk[SCAN_BLOCKS];
__device__ int   g_blkoff[SCAN_BLOCKS];
__device__ int   g_csc_edge[EE];   // bucket-scattered edge ids
__device__ float2 g_fpk[EE];       // per csc slot: {as_float(src), 1/deg_out[src]}
__device__ float2 g_rpk[EE];       // per edge id:  {as_float(dst), wrap-rotated 1/deg_in}
__device__ float g_A[(size_t)NN * ASTRIDE];
__device__ float g_Weff[2][160 * FOUTC];   // [0]=z, [1]=h ; rows = X|T1o|T1i|T2o|T2i

// ---- f32x2 packed FMA helpers (sm_103a) ----
__device__ __forceinline__ u64 pack2(float x) {
    u64 r;
    asm("mov.b64 %0, {%1, %1};" : "=l"(r) : "f"(x));
    return r;
}
__device__ __forceinline__ void fma2(u64& acc, u64 a, u64 b) {
    asm("fma.rn.f32x2 %0, %1, %2, %0;" : "+l"(acc) : "l"(a), "l"(b));
}
__device__ __forceinline__ void unpack2(float& lo, float& hi, u64 v) {
    asm("mov.b64 {%0, %1}, %2;" : "=f"(lo), "=f"(hi) : "l"(v));
}

// ---------------------------------------------------------------------------
__device__ __forceinline__ int lower_bound_src(const int* __restrict__ src, int s) {
    int lo = 0, hi = EE;
    while (lo < hi) {
        int mid = (lo + hi) >> 1;
        if (src[mid] < s) lo = mid + 1; else hi = mid;
    }
    return lo;
}

// Stream-0 head: zero everything the atomic chain touches.
__global__ void k_zero() {
    int i = blockIdx.x * blockDim.x + threadIdx.x;
    if (i < NN) {
        g_deg_in[i] = 0.f;
        g_cnt_in[i] = 0;
        g_tmp[i] = 0;
    }
    if (i == 0) g_M = 0;
}

// Side-stream init: csr_ptr (binary search), deg_out (CSR gather), Weff.
// Independent of the cnt/scan/scatter chain; joined before k_order.
__global__ void k_init(const int* __restrict__ src, const float* __restrict__ ew,
                       const float* __restrict__ Wz, const float* __restrict__ Wh) {
    int t = blockIdx.x * blockDim.x + threadIdx.x;
    if (t <= NN) {
        int lo = lower_bound_src(src, t);
        g_csr_ptr[t] = lo;
        if (t < NN) {
            int hi = lower_bound_src(src, t + 1);
            float sum = 0.f;
            for (int e = lo; e < hi; e++) sum += ew[e];
            g_deg_out[t] = sum;
        }
    }
    // Weff: W shape (2,3,96,64); only first 32 cin-rows live (H==0)
    if (t < 32 * 64) {
        int c = t >> 6, f = t & 63;
#define WI(W, s, k) W[(((s) * 3 + (k)) * 96 + c) * 64 + f]
        g_Weff[0][(0   + c) * 64 + f] = WI(Wz, 0, 0) + WI(Wz, 1, 0);  // X
        g_Weff[0][(32  + c) * 64 + f] = WI(Wz, 0, 1);                 // T1o
        g_Weff[0][(64  + c) * 64 + f] = WI(Wz, 1, 1);                 // T1i
        g_Weff[0][(96  + c) * 64 + f] = WI(Wz, 0, 2);                 // T2o
        g_Weff[0][(128 + c) * 64 + f] = WI(Wz, 1, 2);                 // T2i
        g_Weff[1][(0   + c) * 64 + f] = WI(Wh, 0, 0) + WI(Wh, 1, 0);
        g_Weff[1][(32  + c) * 64 + f] = WI(Wh, 0, 1);
        g_Weff[1][(64  + c) * 64 + f] = WI(Wh, 1, 1);
        g_Weff[1][(96  + c) * 64 + f] = WI(Wh, 0, 2);
        g_Weff[1][(128 + c) * 64 + f] = WI(Wh, 1, 2);
#undef WI
    }
}

// cnt_in histogram (atomics).
__global__ void k_degin(const int* __restrict__ dst) {
    int e = blockIdx.x * blockDim.x + threadIdx.x;
    if (e < EE) atomicAdd(&g_cnt_in[dst[e]], 1);
}

// ---- multi-block exclusive scan of cnt_in -> csc_ptr ----
__global__ void k_scan1() {
    __shared__ int sh[256];
    int tid = threadIdx.x;
    int gid = blockIdx.x * 256 + tid;
    int v = (gid < NN) ? g_cnt_in[gid] : 0;
    sh[tid] = v;
    __syncthreads();
    for (int off = 1; off < 256; off <<= 1) {
        int t = (tid >= off) ? sh[tid - off] : 0;
        __syncthreads();
        sh[tid] += t;
        __syncthreads();
    }
    if (gid < NN) g_csc_ptr[gid] = sh[tid] - v;
    if (tid == 255) g_blk[blockIdx.x] = sh[255];
}

__global__ void k_scan2() {
    __shared__ int sh[256];
    int tid = threadIdx.x;
    int v = (tid < SCAN_BLOCKS) ? g_blk[tid] : 0;
    sh[tid] = v;
    __syncthreads();
    for (int off = 1; off < 256; off <<= 1) {
        int t = (tid >= off) ? sh[tid - off] : 0;
        __syncthreads();
        sh[tid] += t;
        __syncthreads();
    }
    if (tid < SCAN_BLOCKS) g_blkoff[tid] = sh[tid] - v;
}

__global__ void k_scan3() {
    int gid = blockIdx.x * 256 + threadIdx.x;
    if (gid < NN) g_csc_ptr[gid] += g_blkoff[blockIdx.x];
    if (gid == 0) g_csc_ptr[NN] = EE;
}

// Scatter + deg_in accumulation + M-count (ballot).
// jax x64-disabled quirk: argsort key dst*N+src wraps in int32 for key >= 2^31;
// wrapped-key edges sort FIRST. M = #non-wrapping edges.
__global__ void k_scatter(const int* __restrict__ src, const int* __restrict__ dst,
                          const float* __restrict__ ew) {
    __shared__ int sM;
    if (threadIdx.x == 0) sM = 0;
    __syncthreads();
    int e = blockIdx.x * blockDim.x + threadIdx.x;
    bool nw = false;
    if (e < EE) {
        int d = dst[e];
        int pos = g_csc_ptr[d] + atomicAdd(&g_tmp[d], 1);
        g_csc_edge[pos] = e;
        atomicAdd(&g_deg_in[d], ew[e]);
        long long key = (long long)d * NN + (long long)src[e];
        nw = (key < 2147483648LL);
    }
    unsigned b = __ballot_sync(0xffffffffu, nw);
    if ((threadIdx.x & 31) == 0) atomicAdd(&sM, __popc(b));
    __syncthreads();
    if (threadIdx.x == 0) atomicAdd(&g_M, sM);
}

// Warp per dst node. Within a dst bucket, src order == edge-id order (edges
// sorted by (src,dst), pairs unique) -> rank by comparing edge ids via shfl
// (no extra src[] gathers). TRUE position q = beg + r; reference order = wrap
// rotation p = (q - M) mod E; positional quirk: w_rev[e] = 1/deg_in[src[p]]
// with src = ORIGINAL input array indexed at position p.
__global__ void k_order(const int* __restrict__ src) {
    int w = (blockIdx.x * blockDim.x + threadIdx.x) >> 5;
    int lane = threadIdx.x & 31;
    if (w >= NN) return;
    int d = w;
    int beg = g_csc_ptr[d], end = g_csc_ptr[d + 1];
    int deg = end - beg;
    int M = g_M;
    for (int c0 = 0; c0 < deg; c0 += 32) {
        int i = c0 + lane;
        int e = 0x7fffffff;
        if (i < deg) e = g_csc_edge[beg + i];
        int r = 0;
        for (int c1 = 0; c1 < deg; c1 += 32) {
            int j = c1 + lane;
            int ej = (j < deg) ? g_csc_edge[beg + j] : 0x7fffffff;
            int lim = deg - c1; if (lim > 32) lim = 32;
            for (int l = 0; l < lim; l++) {
                int v = __shfl_sync(0xffffffffu, ej, l);
                if (v < e) r++;
            }
        }
        if (i < deg) {
            int p = beg + r - M;
            if (p < 0) p += EE;
            int se = src[e];
            g_rpk[e] = make_float2(__int_as_float(d), 1.0f / g_deg_in[src[p]]);
            g_fpk[beg + i] = make_float2(__int_as_float(se), 1.0f / g_deg_out[se]);
        }
    }
}

// Gather prop, one warp per (node, direction). No atomics.
__global__ __launch_bounds__(256) void k_prop(const float* __restrict__ in, int istride,
                                              const float* __restrict__ X,
                                              int fi, int fo, int ri, int ro,
                                              float coef, int subx) {
    int w = (blockIdx.x * blockDim.x + threadIdx.x) >> 5;
    int lane = threadIdx.x & 31;
    if (w < NN) {
        int d = w;
        int beg = g_csc_ptr[d], end = g_csc_ptr[d + 1];
        float acc = 0.f;
        #pragma unroll 4
        for (int i = beg; i < end; i++) {
            float2 m = g_fpk[i];
            acc += m.y * in[(size_t)__float_as_int(m.x) * istride + fi + lane];
        }
        float r = coef * acc;
        if (subx) r -= X[(size_t)d * 32 + lane];
        g_A[(size_t)d * ASTRIDE + fo + lane] = r;
    } else if (w < 2 * NN) {
        int s = w - NN;
        int beg = g_csr_ptr[s], end = g_csr_ptr[s + 1];
        float acc = 0.f;
        #pragma unroll 4
        for (int e = beg; e < end; e++) {
            float2 m = g_rpk[e];
            acc += m.y * in[(size_t)__float_as_int(m.x) * istride + ri + lane];
        }
        float r = coef * acc;
        if (subx) r -= X[(size_t)s * 32 + lane];
        g_A[(size_t)s * ASTRIDE + ro + lane] = r;
    }
}

// Fused gate GEMM on packed f32x2: 256 threads, 1 node/thread,
// blockIdx.y = column half. Weight tile interleaved [k][g][z0 z1 h0 h1]:
// one LDS.128 (broadcast) feeds 2 FFMA2. 32 u64 accumulators -> no spills.
// out = (1 - sigmoid(z)) * tanh(h).
__global__ __launch_bounds__(256) void k_final(const float* __restrict__ X,
                                               const float* __restrict__ bz,
                                               const float* __restrict__ bh,
                                               float* __restrict__ out) {
    __shared__ float4 wzh[160 * 16];   // 40 KB
    int half = blockIdx.y;
    int tid = threadIdx.x;
    {
        const float2* z2 = (const float2*)g_Weff[0];
        const float2* h2 = (const float2*)g_Weff[1];
        for (int idx = tid; idx < 160 * 16; idx += 256) {
            int k = idx >> 4, g = idx & 15;
            float2 z = z2[k * 32 + half * 16 + g];
            float2 h = h2[k * 32 + half * 16 + g];
            wzh[idx] = make_float4(z.x, z.y, h.x, h.y);
        }
    }
    __syncthreads();

    int n = blockIdx.x * 256 + tid;
    if (n >= NN) return;
    const float4* x4 = (const float4*)(X + (size_t)n * 32);
    const float4* a4 = (const float4*)(g_A + (size_t)n * ASTRIDE);

    u64 az[16], ah[16];
    #pragma unroll
    for (int g = 0; g < 16; g++) { az[g] = 0ULL; ah[g] = 0ULL; }

    for (int k4 = 0; k4 < 40; k4++) {
        float4 av = (k4 < 8) ? x4[k4] : a4[k4 - 8];
        #pragma unroll
        for (int kk = 0; kk < 4; kk++) {
            u64 xx = pack2((&av.x)[kk]);
            const u64* wp = (const u64*)(wzh + (k4 * 4 + kk) * 16);
            #pragma unroll
            for (int g = 0; g < 16; g++) {
                fma2(az[g], wp[2 * g], xx);
                fma2(ah[g], wp[2 * g + 1], xx);
            }
        }
    }

    float* o = out + (size_t)n * FOUTC + half * 32;
    #pragma unroll
    for (int g = 0; g < 16; g++) {
        float zl, zh, hl, hh;
        unpack2(zl, zh, az[g]);
        unpack2(hl, hh, ah[g]);
        float gz0 = zl + bz[half * 32 + 2 * g];
        float gz1 = zh + bz[half * 32 + 2 * g + 1];
        float gh0 = hl + bh[half * 32 + 2 * g];
        float gh1 = hh + bh[half * 32 + 2 * g + 1];
        float k0 = 1.0f - 1.0f / (1.0f + __expf(-gz0));
        float k1 = 1.0f - 1.0f / (1.0f + __expf(-gz1));
        float t0 = 2.0f / (1.0f + __expf(-2.0f * gh0)) - 1.0f;
        float t1 = 2.0f / (1.0f + __expf(-2.0f * gh1)) - 1.0f;
        o[2 * g]     = k0 * t0;
        o[2 * g + 1] = k1 * t1;
    }
}

// ---------------------------------------------------------------------------
extern "C" void kernel_launch(void* const* d_in, const int* in_sizes, int n_in,
                              void* d_out, int out_size) {
    const float* X  = (const float*)d_in[0];
    const int*   ei = (const int*)d_in[1];          // [2, E] row-major
    const float* ew = (const float*)d_in[2];
    const float* Wz = (const float*)d_in[3];
    const float* bz = (const float*)d_in[4];
    // d_in[5]=Wr, d_in[6]=br dead: H==0 -> Z*H==0 and H*R==0
    const float* Wh = (const float*)d_in[7];
    const float* bh = (const float*)d_in[8];
    float* out = (float*)d_out;

    const int* src = ei;
    const int* dst = ei + EE;
    const float* Ag = nullptr;
    cudaGetSymbolAddress((void**)&Ag, g_A);   // host-side query, no device work

    // one-time side-stream resources (handles only; no device memory)
    static cudaStream_t s2 = nullptr;
    static cudaEvent_t evFork = nullptr, evJoin = nullptr;
    if (!s2) {
        cudaStreamCreateWithFlags(&s2, cudaStreamNonBlocking);
        cudaEventCreateWithFlags(&evFork, cudaEventDisableTiming);
        cudaEventCreateWithFlags(&evJoin, cudaEventDisableTiming);
    }

    // fork: k_init runs concurrently with the histogram/scan/scatter chain
    k_zero<<<SCAN_BLOCKS, 256>>>();
    cudaEventRecord(evFork, 0);
    cudaStreamWaitEvent(s2, evFork, 0);
    k_init<<<(NN + 1 + 255) / 256, 256, 0, s2>>>(src, ew, Wz, Wh);
    cudaEventRecord(evJoin, s2);

    k_degin<<<(EE + 255) / 256, 256>>>(dst);
    k_scan1<<<SCAN_BLOCKS, 256>>>();
    k_scan2<<<1, 256>>>();
    k_scan3<<<SCAN_BLOCKS, 256>>>();
    k_scatter<<<(EE + 255) / 256, 256>>>(src, dst, ew);

    // join: k_order needs deg_out/csr (k_init) + csc/deg_in/M (chain)
    cudaStreamWaitEvent(0, evJoin, 0);
    k_order<<<(NN * 32 + 255) / 256, 256>>>(src);

    int prop_blocks = (2 * NN * 32 + 255) / 256;
    // T1o (A cols 0-31) = fwd(X); T1i (32-63) = rev(X)
    k_prop<<<prop_blocks, 256>>>(X, 32, X, 0, 0, 0, 32, 1.0f, 0);
    // T2o (64-95) = 2*fwd(T1o) - X; T2i (96-127) = 2*rev(T1i) - X
    k_prop<<<prop_blocks, 256>>>(Ag, ASTRIDE, X, 0, 64, 32, 96, 2.0f, 1);

    dim3 fgrid((NN + 255) / 256, 2);
    k_final<<<fgrid, 256>>>(X, bz, bh, out);
}